// round 1
// baseline (speedup 1.0000x reference)
#include <cuda_runtime.h>
#include <cstdint>

#define B_DIM 8
#define N_Q 4096
#define C_DIM 256
#define N_HEADS 8
#define HD 32
#define N_K 256
#define ATT_SCALE 0.17677669529663687f  // 1/sqrt(32)

// ---------------- scratch (no allocation allowed) ----------------
__device__ float g_q   [B_DIM * N_Q * C_DIM];      // 33.5 MB  q = x@q_w
__device__ float g_attn[B_DIM * N_Q * C_DIM];      // 33.5 MB  attention output (pre-proj)
__device__ float g_xr  [B_DIM * N_K * C_DIM];      // 2 MB     conv out / LN out
__device__ float g_kv  [B_DIM * N_K * 2 * C_DIM];  // 4 MB     kv = x_ln@kv_w
__device__ float g_w2  [4096 * C_DIM];             // 4 MB     conv weights re-laid as [K=4096][256]

// ---------------- conv weight relayout ----------------
// w2[k][co] with k = (i*4+j)*256 + cin  <-  sr_w[co][cin][i][j] (OIHW)
__global__ void transpose_srw(const float* __restrict__ sr, float* __restrict__ w2) {
    int kk = blockIdx.x;           // 0..4095
    int co = threadIdx.x;          // 0..255
    int cin = kk & 255;
    int pix = kk >> 8;
    w2[kk * 256 + co] = sr[co * 4096 + cin * 16 + pix];
}

// ---------------- generic SGEMM: C[M,N] = A[M,K] @ B[K,N] (+bias) ----------------
// 128x128 tile, BK=8, 256 threads, 8x8 per thread. Requires M%128==0, N%128==0, K%8==0.
template <bool BIAS>
__global__ __launch_bounds__(256)
void sgemm128(const float* __restrict__ A, const float* __restrict__ B,
              const float* __restrict__ bias, float* __restrict__ C,
              int M, int N, int K) {
    __shared__ float As[8][132];   // padded to dodge store conflicts; rows 16B-aligned
    __shared__ float Bs[8][128];

    const int tid = threadIdx.x;
    const int bx = blockIdx.x, by = blockIdx.y;

    const int arow = tid >> 1;           // 0..127
    const int acol = (tid & 1) << 2;     // 0 or 4
    const int brow = tid >> 5;           // 0..7
    const int bcol = (tid & 31) << 2;    // 0..124
    const int tx = tid & 15, ty = tid >> 4;

    const float* Ap = A + (size_t)(by * 128 + arow) * K;
    const float* Bp = B + (size_t)bx * 128;

    float acc[8][8];
#pragma unroll
    for (int i = 0; i < 8; i++)
#pragma unroll
        for (int j = 0; j < 8; j++) acc[i][j] = 0.f;

    for (int k0 = 0; k0 < K; k0 += 8) {
        float4 av = *(const float4*)(Ap + k0 + acol);
        As[acol + 0][arow] = av.x;
        As[acol + 1][arow] = av.y;
        As[acol + 2][arow] = av.z;
        As[acol + 3][arow] = av.w;
        *(float4*)&Bs[brow][bcol] = *(const float4*)(Bp + (size_t)(k0 + brow) * N + bcol);
        __syncthreads();
#pragma unroll
        for (int kk = 0; kk < 8; kk++) {
            float4 a0 = *(float4*)&As[kk][ty * 8];
            float4 a1 = *(float4*)&As[kk][ty * 8 + 4];
            float4 b0 = *(float4*)&Bs[kk][tx * 8];
            float4 b1 = *(float4*)&Bs[kk][tx * 8 + 4];
            float ar[8] = {a0.x, a0.y, a0.z, a0.w, a1.x, a1.y, a1.z, a1.w};
            float br[8] = {b0.x, b0.y, b0.z, b0.w, b1.x, b1.y, b1.z, b1.w};
#pragma unroll
            for (int i = 0; i < 8; i++)
#pragma unroll
                for (int j = 0; j < 8; j++) acc[i][j] += ar[i] * br[j];
        }
        __syncthreads();
    }

#pragma unroll
    for (int i = 0; i < 8; i++) {
        int row = by * 128 + ty * 8 + i;
        float* cp = C + (size_t)row * N + bx * 128 + tx * 8;
        float4 o0, o1;
        if (BIAS) {
            const float* bp = bias + bx * 128 + tx * 8;
            o0 = make_float4(acc[i][0] + bp[0], acc[i][1] + bp[1], acc[i][2] + bp[2], acc[i][3] + bp[3]);
            o1 = make_float4(acc[i][4] + bp[4], acc[i][5] + bp[5], acc[i][6] + bp[6], acc[i][7] + bp[7]);
        } else {
            o0 = make_float4(acc[i][0], acc[i][1], acc[i][2], acc[i][3]);
            o1 = make_float4(acc[i][4], acc[i][5], acc[i][6], acc[i][7]);
        }
        *(float4*)cp = o0;
        *(float4*)(cp + 4) = o1;
    }
}

// ---------------- conv (4x4 / stride 4 / VALID) as implicit-im2col GEMM ----------------
// out[r=(b*256+p)][co] = sum_k x_im2col[r][k] * w2[k][co] + sr_b[co]
// k = pix*256 + cin, token(r,pix) = b*4096 + (4*py+i)*64 + 4*px + j
// M=2048, N=256, K=4096; BM=BN=64, BK=16, 256 threads, 4x4 per thread -> 128 blocks.
__global__ __launch_bounds__(256)
void conv_gemm(const float* __restrict__ x, const float* __restrict__ w2,
               const float* __restrict__ bias, float* __restrict__ out) {
    __shared__ float As[16][68];
    __shared__ float Bs[16][64];

    const int tid = threadIdx.x;
    const int bx = blockIdx.x;   // 0..3 (cols)
    const int by = blockIdx.y;   // 0..31 (rows)

    const int arow = tid >> 2;          // 0..63
    const int acol = (tid & 3) << 2;    // 0,4,8,12
    const int brow = tid >> 4;          // 0..15
    const int bcol = (tid & 15) << 2;   // 0..60
    const int tx = tid & 15, ty = tid >> 4;

    const int r = by * 64 + arow;
    const int b = r >> 8, p = r & 255;
    const int py = p >> 4, px = p & 15;
    const int rowbase = b * 4096 + py * 4 * 64 + px * 4;  // token index of patch (i=0,j=0)

    float acc[4][4];
#pragma unroll
    for (int i = 0; i < 4; i++)
#pragma unroll
        for (int j = 0; j < 4; j++) acc[i][j] = 0.f;

    for (int k0 = 0; k0 < 4096; k0 += 16) {
        int k = k0 + acol;
        int pix = k >> 8;               // constant across the float4
        int pi = pix >> 2, pj = pix & 3;
        int tok = rowbase + pi * 64 + pj;
        float4 av = *(const float4*)(x + (size_t)tok * 256 + (k & 255));
        As[acol + 0][arow] = av.x;
        As[acol + 1][arow] = av.y;
        As[acol + 2][arow] = av.z;
        As[acol + 3][arow] = av.w;
        *(float4*)&Bs[brow][bcol] =
            *(const float4*)(w2 + (size_t)(k0 + brow) * 256 + bx * 64 + bcol);
        __syncthreads();
#pragma unroll
        for (int kk = 0; kk < 16; kk++) {
            float4 a = *(float4*)&As[kk][ty * 4];
            float4 bv = *(float4*)&Bs[kk][tx * 4];
            float ar[4] = {a.x, a.y, a.z, a.w};
            float br[4] = {bv.x, bv.y, bv.z, bv.w};
#pragma unroll
            for (int i = 0; i < 4; i++)
#pragma unroll
                for (int j = 0; j < 4; j++) acc[i][j] += ar[i] * br[j];
        }
        __syncthreads();
    }

#pragma unroll
    for (int i = 0; i < 4; i++) {
        int row = by * 64 + ty * 4 + i;
        int col = bx * 64 + tx * 4;
        float4 o = make_float4(acc[i][0] + bias[col + 0], acc[i][1] + bias[col + 1],
                               acc[i][2] + bias[col + 2], acc[i][3] + bias[col + 3]);
        *(float4*)(out + (size_t)row * 256 + col) = o;
    }
}

// ---------------- LayerNorm over C=256 (in place), 1 block per row ----------------
__global__ void ln_kernel(float* __restrict__ xr, const float* __restrict__ w,
                          const float* __restrict__ bvec) {
    __shared__ float red[18];
    const int r = blockIdx.x, c = threadIdx.x;
    float v = xr[(size_t)r * 256 + c];
    float s1 = v, s2 = v * v;
#pragma unroll
    for (int off = 16; off; off >>= 1) {
        s1 += __shfl_xor_sync(~0u, s1, off);
        s2 += __shfl_xor_sync(~0u, s2, off);
    }
    int wid = c >> 5;
    if ((c & 31) == 0) { red[wid] = s1; red[8 + wid] = s2; }
    __syncthreads();
    if (c == 0) {
        float a = 0.f, q = 0.f;
#pragma unroll
        for (int i = 0; i < 8; i++) { a += red[i]; q += red[8 + i]; }
        red[16] = a; red[17] = q;
    }
    __syncthreads();
    float mu = red[16] * (1.0f / 256.0f);
    float var = red[17] * (1.0f / 256.0f) - mu * mu;
    xr[(size_t)r * 256 + c] = (v - mu) * rsqrtf(var + 1e-5f) * w[c] + bvec[c];
}

// ---------------- fused attention ----------------
// grid (32 q-tiles, 8 heads, 8 batch), 512 threads.
// SMEM: QsT[32][128], KsT[32][256], Vs[256][32], Ps[128][260], Rinv[128]
__global__ __launch_bounds__(512)
void attn_kernel(const float* __restrict__ q, const float* __restrict__ kv,
                 float* __restrict__ outp) {
    extern __shared__ float sm[];
    float* QsT = sm;            // 4096
    float* KsT = sm + 4096;     // 8192
    float* Vs  = sm + 12288;    // 8192
    float* Ps  = sm + 20480;    // 128*260 = 33280
    float* Rinv = sm + 53760;   // 128

    const int tid = threadIdx.x;
    const int qt = blockIdx.x, h = blockIdx.y, b = blockIdx.z;
    const size_t qbase = (size_t)b * 4096 + (size_t)qt * 128;
    const size_t kvbase = (size_t)b * 256;
    const int hoff = h * 32;

    // load Q tile (128x32) transposed
    for (int idx = tid; idx < 1024; idx += 512) {
        int row = idx >> 3, dq = (idx & 7) << 2;
        float4 v = *(const float4*)(q + (qbase + row) * 256 + hoff + dq);
        QsT[(dq + 0) * 128 + row] = v.x;
        QsT[(dq + 1) * 128 + row] = v.y;
        QsT[(dq + 2) * 128 + row] = v.z;
        QsT[(dq + 3) * 128 + row] = v.w;
    }
    // load K (transposed) and V (row-major)
    for (int idx = tid; idx < 2048; idx += 512) {
        int row = idx >> 3, dq = (idx & 7) << 2;
        const float* base = kv + (kvbase + row) * 512 + hoff + dq;
        float4 kvv = *(const float4*)(base);
        KsT[(dq + 0) * 256 + row] = kvv.x;
        KsT[(dq + 1) * 256 + row] = kvv.y;
        KsT[(dq + 2) * 256 + row] = kvv.z;
        KsT[(dq + 3) * 256 + row] = kvv.w;
        *(float4*)&Vs[row * 32 + dq] = *(const float4*)(base + 256);
    }
    __syncthreads();

    // phase 1: S = Q@K^T  (each thread 8q x 8k; a warp owns 8 full rows)
    const int tk = tid & 31, tq = tid >> 5;
    float s[8][8];
#pragma unroll
    for (int i = 0; i < 8; i++)
#pragma unroll
        for (int j = 0; j < 8; j++) s[i][j] = 0.f;

    for (int d = 0; d < 32; d++) {
        float4 q0 = *(float4*)&QsT[d * 128 + tq * 8];
        float4 q1 = *(float4*)&QsT[d * 128 + tq * 8 + 4];
        float4 k0 = *(float4*)&KsT[d * 256 + tk * 8];
        float4 k1 = *(float4*)&KsT[d * 256 + tk * 8 + 4];
        float qa[8] = {q0.x, q0.y, q0.z, q0.w, q1.x, q1.y, q1.z, q1.w};
        float ka[8] = {k0.x, k0.y, k0.z, k0.w, k1.x, k1.y, k1.z, k1.w};
#pragma unroll
        for (int i = 0; i < 8; i++)
#pragma unroll
            for (int j = 0; j < 8; j++) s[i][j] += qa[i] * ka[j];
    }

    // softmax per row (row fully inside one warp); defer /sum to epilogue
#pragma unroll
    for (int ii = 0; ii < 8; ii++) {
        float m = s[ii][0];
#pragma unroll
        for (int jj = 1; jj < 8; jj++) m = fmaxf(m, s[ii][jj]);
#pragma unroll
        for (int off = 16; off; off >>= 1) m = fmaxf(m, __shfl_xor_sync(~0u, m, off));
        float sum = 0.f;
#pragma unroll
        for (int jj = 0; jj < 8; jj++) {
            float e = __expf((s[ii][jj] - m) * ATT_SCALE);
            s[ii][jj] = e;
            sum += e;
        }
#pragma unroll
        for (int off = 16; off; off >>= 1) sum += __shfl_xor_sync(~0u, sum, off);
        if (tk == 0) Rinv[tq * 8 + ii] = 1.0f / sum;
        float* pr = &Ps[(size_t)(tq * 8 + ii) * 260 + tk * 8];
        *(float4*)pr = make_float4(s[ii][0], s[ii][1], s[ii][2], s[ii][3]);
        *(float4*)(pr + 4) = make_float4(s[ii][4], s[ii][5], s[ii][6], s[ii][7]);
    }
    __syncthreads();

    // phase 2: O = P @ V  (thread = (qg, d): 8 rows x 1 dim)
    const int d = tid & 31;
    const int qg = tid >> 5;
    float o[8] = {0.f, 0.f, 0.f, 0.f, 0.f, 0.f, 0.f, 0.f};
    for (int j = 0; j < 256; j += 4) {
        float v0 = Vs[j * 32 + d];
        float v1 = Vs[(j + 1) * 32 + d];
        float v2 = Vs[(j + 2) * 32 + d];
        float v3 = Vs[(j + 3) * 32 + d];
#pragma unroll
        for (int rr = 0; rr < 8; rr++) {
            float4 pv = *(float4*)&Ps[(size_t)(qg * 8 + rr) * 260 + j];
            o[rr] += pv.x * v0 + pv.y * v1 + pv.z * v2 + pv.w * v3;
        }
    }
#pragma unroll
    for (int rr = 0; rr < 8; rr++) {
        int row = qg * 8 + rr;
        outp[(qbase + row) * 256 + hoff + d] = o[rr] * Rinv[row];
    }
}

// ---------------- launch ----------------
static const size_t ATTN_SMEM = (size_t)(53760 + 128) * sizeof(float);  // 215,552 B

extern "C" void kernel_launch(void* const* d_in, const int* in_sizes, int n_in,
                              void* d_out, int out_size) {
    // inputs in reference order: x, H, W, q_w, kv_w, sr_w, sr_b, ln_w, ln_b, proj_w, proj_b
    // scalars (size 1) may or may not appear; assign by skipping size-1 entries after x.
    const float* ptrs[9] = {nullptr};
    int pi = 0;
    for (int i = 0; i < n_in && pi < 9; i++) {
        if (in_sizes[i] == 1) continue;  // H, W scalars
        ptrs[pi++] = (const float*)d_in[i];
    }
    const float* x      = ptrs[0];
    const float* q_w    = ptrs[1];
    const float* kv_w   = ptrs[2];
    const float* sr_w   = ptrs[3];
    const float* sr_b   = ptrs[4];
    const float* ln_w   = ptrs[5];
    const float* ln_b   = ptrs[6];
    const float* proj_w = ptrs[7];
    const float* proj_b = ptrs[8];
    float* out = (float*)d_out;

    float *pq, *pattn, *pxr, *pkv, *pw2;
    cudaGetSymbolAddress((void**)&pq, g_q);
    cudaGetSymbolAddress((void**)&pattn, g_attn);
    cudaGetSymbolAddress((void**)&pxr, g_xr);
    cudaGetSymbolAddress((void**)&pkv, g_kv);
    cudaGetSymbolAddress((void**)&pw2, g_w2);

    cudaFuncSetAttribute(attn_kernel, cudaFuncAttributeMaxDynamicSharedMemorySize,
                         (int)ATTN_SMEM);

    // 1. conv weight relayout
    transpose_srw<<<4096, 256>>>(sr_w, pw2);
    // 2. q = x @ q_w                     [32768,256] @ [256,256]
    sgemm128<false><<<dim3(2, 256), 256>>>(x, q_w, nullptr, pq, 32768, 256, 256);
    // 3. conv (implicit im2col GEMM) + bias -> g_xr [2048,256]
    conv_gemm<<<dim3(4, 32), 256>>>(x, pw2, sr_b, pxr);
    // 4. LayerNorm in place
    ln_kernel<<<2048, 256>>>(pxr, ln_w, ln_b);
    // 5. kv = x_ln @ kv_w                [2048,256] @ [256,512]
    sgemm128<false><<<dim3(4, 16), 256>>>(pxr, kv_w, nullptr, pkv, 2048, 512, 256);
    // 6. fused softmax attention -> g_attn [B,N,C] (head-interleaved layout)
    attn_kernel<<<dim3(32, 8, 8), 512, ATTN_SMEM>>>(pq, pkv, pattn);
    // 7. out = attn @ proj_w + proj_b
    sgemm128<true><<<dim3(2, 256), 256>>>(pattn, proj_w, proj_b, out, 32768, 256, 256);
}

// round 3
// speedup vs baseline: 3.0068x; 3.0068x over previous
#include <cuda_runtime.h>
#include <cstdint>

#define ATT_SCALE 0.17677669529663687f   // 1/sqrt(32)
#define ATT_C2    0.25506238539520833f   // ATT_SCALE * log2(e)
#define SPLITK 8

// ---------------- scratch (no allocation allowed) ----------------
__device__ float g_q    [8 * 4096 * 256];
__device__ float g_attn [8 * 4096 * 256];
__device__ float g_xr   [8 * 256 * 256];
__device__ float g_kv   [8 * 256 * 512];
__device__ float g_w2t  [256 * 4096];         // conv weights [co][k=pix*256+cin]
__device__ float g_qwT  [256 * 256];
__device__ float g_pwT  [256 * 256];
__device__ float g_kvwT [512 * 256];
__device__ float g_part [SPLITK * 2048 * 256];

// ================= helpers =================
__device__ __forceinline__ uint32_t f2tf(float f) {
    uint32_t u;
    asm("cvt.rna.tf32.f32 %0, %1;" : "=r"(u) : "f"(f));
    return u;
}
__device__ __forceinline__ float ex2(float x) {
    float y;
    asm("ex2.approx.f32 %0, %1;" : "=f"(y) : "f"(x));
    return y;
}
// D += A@B  (m16n8k8 tf32).  a0=A[g][t] a1=A[g+8][t] a2=A[g][t+4] a3=A[g+8][t+4]
// b0=B[t][g] b1=B[t+4][g]    c0=C[g][2t] c1=C[g][2t+1] c2=C[g+8][2t] c3=C[g+8][2t+1]
__device__ __forceinline__ void mma8(float* d, const uint32_t* a, const uint32_t* b) {
    asm volatile(
        "mma.sync.aligned.m16n8k8.row.col.f32.tf32.tf32.f32 "
        "{%0,%1,%2,%3}, {%4,%5,%6,%7}, {%8,%9}, {%0,%1,%2,%3};"
        : "+f"(d[0]), "+f"(d[1]), "+f"(d[2]), "+f"(d[3])
        : "r"(a[0]), "r"(a[1]), "r"(a[2]), "r"(a[3]), "r"(b[0]), "r"(b[1]));
}

// ===== weight prep =====
__global__ void transpose_naive(const float* __restrict__ in, float* __restrict__ out,
                                int R, int Ccols) {
    int t = blockIdx.x * 256 + threadIdx.x;
    if (t < R * Ccols) {
        int n = t / R, k = t % R;
        out[t] = in[k * Ccols + n];
    }
}
__global__ void relayout_srw(const float* __restrict__ sr, float* __restrict__ w2t) {
    int t = blockIdx.x * 256 + threadIdx.x;  // 256*4096
    int co = t >> 12, rem = t & 4095;
    int pix = rem >> 8, cin = rem & 255;
    w2t[t] = sr[co * 4096 + cin * 16 + pix];
}

// ===== dense GEMM via mma.sync tf32: C[M,Nout] = A[M,K] @ Bt[Nout,K]^T (+bias) =====
// CTA tile 128x128, BK=32, 256 threads = 8 warps (2M x 4N), warp tile 64x32.
template <bool BIAS>
__global__ __launch_bounds__(256, 2)
void gemm_mma(const float* __restrict__ A, const float* __restrict__ Bt,
              const float* __restrict__ bias, float* __restrict__ C,
              int K, int Nout) {
    __shared__ uint32_t As[128][36];
    __shared__ uint32_t Bs[128][36];

    const int tid = threadIdx.x, lane = tid & 31, warp = tid >> 5;
    const int g = lane >> 2, t = lane & 3;
    const int wm = warp >> 2, wn = warp & 3;
    const int mbase = blockIdx.y * 128, nbase = blockIdx.x * 128;

    const float* Ab = A + (size_t)mbase * K;
    const float* Bb = Bt + (size_t)nbase * K;

    float cs[4][4][4];
#pragma unroll
    for (int i = 0; i < 4; i++)
#pragma unroll
        for (int j = 0; j < 4; j++)
#pragma unroll
            for (int q = 0; q < 4; q++) cs[i][j][q] = 0.f;

    for (int k0 = 0; k0 < K; k0 += 32) {
#pragma unroll
        for (int i = 0; i < 4; i++) {
            int idx = tid + i * 256;
            int r = idx >> 3, c = (idx & 7) << 2;
            float4 v = *(const float4*)(Ab + (size_t)r * K + k0 + c);
            *(uint4*)&As[r][c] = make_uint4(f2tf(v.x), f2tf(v.y), f2tf(v.z), f2tf(v.w));
        }
#pragma unroll
        for (int i = 0; i < 4; i++) {
            int idx = tid + i * 256;
            int r = idx >> 3, c = (idx & 7) << 2;
            float4 v = *(const float4*)(Bb + (size_t)r * K + k0 + c);
            *(uint4*)&Bs[r][c] = make_uint4(f2tf(v.x), f2tf(v.y), f2tf(v.z), f2tf(v.w));
        }
        __syncthreads();
#pragma unroll
        for (int ks = 0; ks < 4; ks++) {
            const int kk = ks * 8 + t;
            uint32_t af[4][4], bf[4][2];
#pragma unroll
            for (int mt = 0; mt < 4; mt++) {
                int row = wm * 64 + mt * 16;
                af[mt][0] = As[row + g][kk];
                af[mt][1] = As[row + g + 8][kk];
                af[mt][2] = As[row + g][kk + 4];
                af[mt][3] = As[row + g + 8][kk + 4];
            }
#pragma unroll
            for (int nt = 0; nt < 4; nt++) {
                int rb = wn * 32 + nt * 8 + g;
                bf[nt][0] = Bs[rb][kk];
                bf[nt][1] = Bs[rb][kk + 4];
            }
#pragma unroll
            for (int mt = 0; mt < 4; mt++)
#pragma unroll
                for (int nt = 0; nt < 4; nt++) mma8(cs[mt][nt], af[mt], bf[nt]);
        }
        __syncthreads();
    }

#pragma unroll
    for (int mt = 0; mt < 4; mt++) {
        int row = mbase + wm * 64 + mt * 16 + g;
#pragma unroll
        for (int nt = 0; nt < 4; nt++) {
            int col = nbase + wn * 32 + nt * 8 + 2 * t;
            float b0 = 0.f, b1 = 0.f;
            if (BIAS) { b0 = __ldg(bias + col); b1 = __ldg(bias + col + 1); }
            *(float2*)(C + (size_t)row * Nout + col) =
                make_float2(cs[mt][nt][0] + b0, cs[mt][nt][1] + b1);
            *(float2*)(C + (size_t)(row + 8) * Nout + col) =
                make_float2(cs[mt][nt][2] + b0, cs[mt][nt][3] + b1);
        }
    }
}

// ===== conv (4x4/stride4 im2col) mma GEMM, split-K=8 -> partials =====
// M=2048, N=256, K=4096; grid (2, 16, 8); K-chunk 512 = 16 stages of 32.
__global__ __launch_bounds__(256, 2)
void conv_mma(const float* __restrict__ x, const float* __restrict__ w2t,
              float* __restrict__ part) {
    __shared__ uint32_t As[128][36];
    __shared__ uint32_t Bs[128][36];

    const int tid = threadIdx.x, lane = tid & 31, warp = tid >> 5;
    const int g = lane >> 2, t = lane & 3;
    const int wm = warp >> 2, wn = warp & 3;
    const int mbase = blockIdx.y * 128, nbase = blockIdx.x * 128;
    const int kz = blockIdx.z;

    float cs[4][4][4];
#pragma unroll
    for (int i = 0; i < 4; i++)
#pragma unroll
        for (int j = 0; j < 4; j++)
#pragma unroll
            for (int q = 0; q < 4; q++) cs[i][j][q] = 0.f;

    for (int s = 0; s < 16; s++) {
        const int kg = kz * 512 + s * 32;
        const int pix = kg >> 8, cin0 = kg & 255;
        const int pi = pix >> 2, pj = pix & 3;
#pragma unroll
        for (int i = 0; i < 4; i++) {
            int idx = tid + i * 256;
            int r = idx >> 3, c = (idx & 7) << 2;
            int m = mbase + r;
            int b = m >> 8, p = m & 255;
            int tok = b * 4096 + (p >> 4) * 256 + (p & 15) * 4 + pi * 64 + pj;
            float4 v = *(const float4*)(x + (size_t)tok * 256 + cin0 + c);
            *(uint4*)&As[r][c] = make_uint4(f2tf(v.x), f2tf(v.y), f2tf(v.z), f2tf(v.w));
        }
#pragma unroll
        for (int i = 0; i < 4; i++) {
            int idx = tid + i * 256;
            int r = idx >> 3, c = (idx & 7) << 2;
            float4 v = *(const float4*)(w2t + (size_t)(nbase + r) * 4096 + kg + c);
            *(uint4*)&Bs[r][c] = make_uint4(f2tf(v.x), f2tf(v.y), f2tf(v.z), f2tf(v.w));
        }
        __syncthreads();
#pragma unroll
        for (int ks = 0; ks < 4; ks++) {
            const int kk = ks * 8 + t;
            uint32_t af[4][4], bf[4][2];
#pragma unroll
            for (int mt = 0; mt < 4; mt++) {
                int row = wm * 64 + mt * 16;
                af[mt][0] = As[row + g][kk];
                af[mt][1] = As[row + g + 8][kk];
                af[mt][2] = As[row + g][kk + 4];
                af[mt][3] = As[row + g + 8][kk + 4];
            }
#pragma unroll
            for (int nt = 0; nt < 4; nt++) {
                int rb = wn * 32 + nt * 8 + g;
                bf[nt][0] = Bs[rb][kk];
                bf[nt][1] = Bs[rb][kk + 4];
            }
#pragma unroll
            for (int mt = 0; mt < 4; mt++)
#pragma unroll
                for (int nt = 0; nt < 4; nt++) mma8(cs[mt][nt], af[mt], bf[nt]);
        }
        __syncthreads();
    }

    float* outp = part + (size_t)kz * 2048 * 256;
#pragma unroll
    for (int mt = 0; mt < 4; mt++) {
        int row = mbase + wm * 64 + mt * 16 + g;
#pragma unroll
        for (int nt = 0; nt < 4; nt++) {
            int col = nbase + wn * 32 + nt * 8 + 2 * t;
            *(float2*)(outp + (size_t)row * 256 + col) = make_float2(cs[mt][nt][0], cs[mt][nt][1]);
            *(float2*)(outp + (size_t)(row + 8) * 256 + col) = make_float2(cs[mt][nt][2], cs[mt][nt][3]);
        }
    }
}

// ===== split-K reduce + bias + LayerNorm =====
__global__ void reduce_ln(const float* __restrict__ part, const float* __restrict__ bias,
                          const float* __restrict__ w, const float* __restrict__ bvec,
                          float* __restrict__ xr) {
    __shared__ float red[18];
    const int r = blockIdx.x, c = threadIdx.x;
    float v = bias[c];
#pragma unroll
    for (int z = 0; z < SPLITK; z++)
        v += part[(size_t)z * 2048 * 256 + (size_t)r * 256 + c];
    float s1 = v, s2 = v * v;
#pragma unroll
    for (int off = 16; off; off >>= 1) {
        s1 += __shfl_xor_sync(~0u, s1, off);
        s2 += __shfl_xor_sync(~0u, s2, off);
    }
    int wid = c >> 5;
    if ((c & 31) == 0) { red[wid] = s1; red[8 + wid] = s2; }
    __syncthreads();
    if (c == 0) {
        float a = 0.f, q = 0.f;
#pragma unroll
        for (int i = 0; i < 8; i++) { a += red[i]; q += red[8 + i]; }
        red[16] = a; red[17] = q;
    }
    __syncthreads();
    float mu = red[16] * (1.0f / 256.0f);
    float var = red[17] * (1.0f / 256.0f) - mu * mu;
    xr[(size_t)r * 256 + c] = (v - mu) * rsqrtf(var + 1e-5f) * w[c] + bvec[c];
}

// ===== fused attention via mma.sync tf32 =====
// grid (32 q-tiles, 8 heads, 8 batch), 256 threads = 8 warps, warp owns 16 q-rows.
// dyn smem: Ks[256][36], Vs[256][40], Ps[8 warps][16][36]  = 96,256 B
#define ATTN_SMEM 96256
__global__ __launch_bounds__(256)
void attn_mma(const float* __restrict__ q, const float* __restrict__ kv,
              float* __restrict__ outp) {
    extern __shared__ uint32_t dsm[];
    uint32_t(*Ks)[36] = (uint32_t(*)[36])dsm;
    uint32_t(*Vs)[40] = (uint32_t(*)[40])(dsm + 256 * 36);

    const int tid = threadIdx.x, lane = tid & 31, warp = tid >> 5;
    const int g = lane >> 2, t = lane & 3;
    uint32_t(*Pw)[36] = (uint32_t(*)[36])(dsm + 256 * 36 + 256 * 40 + warp * 16 * 36);

    const int qt = blockIdx.x, h = blockIdx.y, b = blockIdx.z;
    const size_t qbase = (size_t)b * 4096 + (size_t)qt * 128;
    const size_t kvb = (size_t)b * 256;
    const int hoff = h * 32;

    // K,V -> SMEM (tf32)
    for (int idx = tid; idx < 2048; idx += 256) {
        int tok = idx >> 3, c = (idx & 7) << 2;
        const float* base = kv + (kvb + tok) * 512 + hoff + c;
        float4 kk = *(const float4*)base;
        float4 vv = *(const float4*)(base + 256);
        *(uint4*)&Ks[tok][c] = make_uint4(f2tf(kk.x), f2tf(kk.y), f2tf(kk.z), f2tf(kk.w));
        *(uint4*)&Vs[tok][c] = make_uint4(f2tf(vv.x), f2tf(vv.y), f2tf(vv.z), f2tf(vv.w));
    }
    // Q fragments direct from global (warp-private rows)
    uint32_t aq[4][4];
    const int qr = (int)qbase + warp * 16 + g;
    const float* qp = q + (size_t)qr * 256 + hoff;
#pragma unroll
    for (int ks = 0; ks < 4; ks++) {
        aq[ks][0] = f2tf(qp[ks * 8 + t]);
        aq[ks][1] = f2tf(qp[8 * 256 + ks * 8 + t]);
        aq[ks][2] = f2tf(qp[ks * 8 + t + 4]);
        aq[ks][3] = f2tf(qp[8 * 256 + ks * 8 + t + 4]);
    }
    __syncthreads();

    // S = Q @ K^T   (32 n-tiles of 8 tokens)
    float cs[32][4];
#pragma unroll
    for (int j = 0; j < 32; j++)
#pragma unroll
        for (int qq = 0; qq < 4; qq++) cs[j][qq] = 0.f;
#pragma unroll
    for (int ks = 0; ks < 4; ks++) {
        const int kk = ks * 8 + t;
#pragma unroll
        for (int j = 0; j < 32; j++) {
            uint32_t bf[2] = {Ks[j * 8 + g][kk], Ks[j * 8 + g][kk + 4]};
            mma8(cs[j], aq[ks], bf);
        }
    }

    // softmax (rows g and g+8 of this warp's 16-row block; quad = lanes g*4+t)
    float mlo = -1e30f, mhi = -1e30f;
#pragma unroll
    for (int j = 0; j < 32; j++) {
        mlo = fmaxf(mlo, fmaxf(cs[j][0], cs[j][1]));
        mhi = fmaxf(mhi, fmaxf(cs[j][2], cs[j][3]));
    }
    mlo = fmaxf(mlo, __shfl_xor_sync(~0u, mlo, 1));
    mlo = fmaxf(mlo, __shfl_xor_sync(~0u, mlo, 2));
    mhi = fmaxf(mhi, __shfl_xor_sync(~0u, mhi, 1));
    mhi = fmaxf(mhi, __shfl_xor_sync(~0u, mhi, 2));
    float slo = 0.f, shi = 0.f;
#pragma unroll
    for (int j = 0; j < 32; j++) {
        cs[j][0] = ex2((cs[j][0] - mlo) * ATT_C2);
        cs[j][1] = ex2((cs[j][1] - mlo) * ATT_C2);
        cs[j][2] = ex2((cs[j][2] - mhi) * ATT_C2);
        cs[j][3] = ex2((cs[j][3] - mhi) * ATT_C2);
        slo += cs[j][0] + cs[j][1];
        shi += cs[j][2] + cs[j][3];
    }
    slo += __shfl_xor_sync(~0u, slo, 1);
    slo += __shfl_xor_sync(~0u, slo, 2);
    shi += __shfl_xor_sync(~0u, shi, 1);
    shi += __shfl_xor_sync(~0u, shi, 2);
    const float rlo = 1.0f / slo, rhi = 1.0f / shi;

    // O = P @ V, streaming 32-token panels through warp-private SMEM
    float co[4][4];
#pragma unroll
    for (int nt = 0; nt < 4; nt++)
#pragma unroll
        for (int qq = 0; qq < 4; qq++) co[nt][qq] = 0.f;

#pragma unroll
    for (int p = 0; p < 8; p++) {
#pragma unroll
        for (int jj = 0; jj < 4; jj++) {
            const int j = p * 4 + jj, lc = jj * 8;
            Pw[g][lc + 2 * t] = f2tf(cs[j][0]);
            Pw[g][lc + 2 * t + 1] = f2tf(cs[j][1]);
            Pw[g + 8][lc + 2 * t] = f2tf(cs[j][2]);
            Pw[g + 8][lc + 2 * t + 1] = f2tf(cs[j][3]);
        }
        __syncwarp();
#pragma unroll
        for (int ks = 0; ks < 4; ks++) {
            const int kk = ks * 8 + t;
            uint32_t ap[4] = {Pw[g][kk], Pw[g + 8][kk], Pw[g][kk + 4], Pw[g + 8][kk + 4]};
            const int tokb = p * 32 + ks * 8;
#pragma unroll
            for (int nt = 0; nt < 4; nt++) {
                uint32_t bf[2] = {Vs[tokb + t][nt * 8 + g], Vs[tokb + t + 4][nt * 8 + g]};
                mma8(co[nt], ap, bf);
            }
        }
        __syncwarp();
    }

    // epilogue
    float* op = outp + (size_t)qr * 256 + hoff;
#pragma unroll
    for (int nt = 0; nt < 4; nt++) {
        *(float2*)(op + nt * 8 + 2 * t) = make_float2(co[nt][0] * rlo, co[nt][1] * rlo);
        *(float2*)(op + 8 * 256 + nt * 8 + 2 * t) = make_float2(co[nt][2] * rhi, co[nt][3] * rhi);
    }
}

// ---------------- launch ----------------
extern "C" void kernel_launch(void* const* d_in, const int* in_sizes, int n_in,
                              void* d_out, int out_size) {
    const float* ptrs[9] = {nullptr};
    int pi = 0;
    for (int i = 0; i < n_in && pi < 9; i++) {
        if (in_sizes[i] == 1) continue;  // H, W scalars
        ptrs[pi++] = (const float*)d_in[i];
    }
    const float* x      = ptrs[0];
    const float* q_w    = ptrs[1];
    const float* kv_w   = ptrs[2];
    const float* sr_w   = ptrs[3];
    const float* sr_b   = ptrs[4];
    const float* ln_w   = ptrs[5];
    const float* ln_b   = ptrs[6];
    const float* proj_w = ptrs[7];
    const float* proj_b = ptrs[8];
    float* out = (float*)d_out;

    float *pq, *pattn, *pxr, *pkv, *pw2t, *pqwT, *ppwT, *pkvwT, *ppart;
    cudaGetSymbolAddress((void**)&pq, g_q);
    cudaGetSymbolAddress((void**)&pattn, g_attn);
    cudaGetSymbolAddress((void**)&pxr, g_xr);
    cudaGetSymbolAddress((void**)&pkv, g_kv);
    cudaGetSymbolAddress((void**)&pw2t, g_w2t);
    cudaGetSymbolAddress((void**)&pqwT, g_qwT);
    cudaGetSymbolAddress((void**)&ppwT, g_pwT);
    cudaGetSymbolAddress((void**)&pkvwT, g_kvwT);
    cudaGetSymbolAddress((void**)&ppart, g_part);

    cudaFuncSetAttribute(attn_mma, cudaFuncAttributeMaxDynamicSharedMemorySize, ATTN_SMEM);

    // weight prep
    transpose_naive<<<256, 256>>>(q_w, pqwT, 256, 256);
    transpose_naive<<<256, 256>>>(proj_w, ppwT, 256, 256);
    transpose_naive<<<512, 256>>>(kv_w, pkvwT, 256, 512);
    relayout_srw<<<4096, 256>>>(sr_w, pw2t);

    // q = x @ q_w
    gemm_mma<false><<<dim3(2, 256), 256>>>(x, pqwT, nullptr, pq, 256, 256);
    // conv partials
    conv_mma<<<dim3(2, 16, SPLITK), 256>>>(x, pw2t, ppart);
    // reduce + bias + LN
    reduce_ln<<<2048, 256>>>(ppart, sr_b, ln_w, ln_b, pxr);
    // kv = xr @ kv_w
    gemm_mma<false><<<dim3(4, 16), 256>>>(pxr, pkvwT, nullptr, pkv, 256, 512);
    // attention
    attn_mma<<<dim3(32, 8, 8), 256, ATTN_SMEM>>>(pq, pkv, pattn);
    // out = attn @ proj_w + proj_b
    gemm_mma<true><<<dim3(2, 256), 256>>>(pattn, ppwT, proj_b, out, 256, 256);
}

// round 5
// speedup vs baseline: 3.7301x; 1.2405x over previous
#include <cuda_runtime.h>
#include <cstdint>

#define ATT_C2 0.25506238539520833f   // (1/sqrt(32)) * log2(e)
#define SPLITK 8

// ---------------- scratch (no allocation allowed) ----------------
// arrays marked (tf32) hold tf32 bit patterns reinterpreted as float
__device__ float g_q    [8 * 4096 * 256];     // (tf32) q
__device__ float g_attn [8 * 4096 * 256];     // (tf32) attention out
__device__ float g_xr   [8 * 256 * 256];      // (tf32) LN out
__device__ float g_kv   [8 * 256 * 512];      // (tf32) kv
__device__ float g_w2t  [256 * 4096];         // (tf32) conv weights [co][pix*256+cin]
__device__ float g_qwT  [256 * 256];          // (tf32)
__device__ float g_pwT  [256 * 256];          // (tf32)
__device__ float g_kvwT [512 * 256];          // (tf32)
__device__ float g_part [SPLITK * 2048 * 256];  // f32 conv partials

// ================= helpers =================
__device__ __forceinline__ uint32_t f2tf(float f) {
    uint32_t u;
    asm("cvt.rna.tf32.f32 %0, %1;" : "=r"(u) : "f"(f));
    return u;
}
__device__ __forceinline__ float ex2(float x) {
    float y;
    asm("ex2.approx.f32 %0, %1;" : "=f"(y) : "f"(x));
    return y;
}
__device__ __forceinline__ uint32_t smem_u32(const void* p) {
    uint32_t a;
    asm("{ .reg .u64 t; cvta.to.shared.u64 t, %1; cvt.u32.u64 %0, t; }" : "=r"(a) : "l"(p));
    return a;
}
__device__ __forceinline__ void cpa16(uint32_t d, const void* s) {
    asm volatile("cp.async.ca.shared.global [%0], [%1], 16;" :: "r"(d), "l"(s) : "memory");
}
__device__ __forceinline__ void cp_commit() {
    asm volatile("cp.async.commit_group;" ::: "memory");
}
template <int N>
__device__ __forceinline__ void cp_wait() {
    asm volatile("cp.async.wait_group %0;" :: "n"(N) : "memory");
}
// D += A@B  (m16n8k8 tf32)
__device__ __forceinline__ void mma8(float* d, const uint32_t* a, const uint32_t* b) {
    asm volatile(
        "mma.sync.aligned.m16n8k8.row.col.f32.tf32.tf32.f32 "
        "{%0,%1,%2,%3}, {%4,%5,%6,%7}, {%8,%9}, {%0,%1,%2,%3};"
        : "+f"(d[0]), "+f"(d[1]), "+f"(d[2]), "+f"(d[3])
        : "r"(a[0]), "r"(a[1]), "r"(a[2]), "r"(a[3]), "r"(b[0]), "r"(b[1]));
}

// ===== fused weight prep: all transposes + relayout, output tf32 bits =====
__global__ void prep_all(const float* __restrict__ qw, const float* __restrict__ pw,
                         const float* __restrict__ kvw, const float* __restrict__ srw,
                         float* __restrict__ qwT, float* __restrict__ pwT,
                         float* __restrict__ kvwT, float* __restrict__ w2t) {
    int t = blockIdx.x * 256 + threadIdx.x;
    if (t < 65536) {
        int n = t >> 8, k = t & 255;
        qwT[t] = __uint_as_float(f2tf(qw[k * 256 + n]));
    } else if (t < 131072) {
        int u = t - 65536;
        int n = u >> 8, k = u & 255;
        pwT[u] = __uint_as_float(f2tf(pw[k * 256 + n]));
    } else if (t < 262144) {
        int u = t - 131072;
        int n = u >> 8, k = u & 255;
        kvwT[u] = __uint_as_float(f2tf(kvw[k * 512 + n]));
    } else {
        int u = t - 262144;  // < 1048576
        int co = u >> 12, rem = u & 4095;
        int pix = rem >> 8, cin = rem & 255;
        w2t[u] = __uint_as_float(f2tf(srw[co * 4096 + cin * 16 + pix]));
    }
}

// ===== pipelined tf32 GEMM: C[M,Nout] = A[M,K] @ Bt[Nout,K]^T =====
// CTA 128x128, BK=32, 256 thr = 8 warps (2M x 4N), 2-stage cp.async pipeline.
// ACVT: A is f32, convert on store to SMEM. else A already tf32 bits (cp.async).
// OTF: store output as tf32 bits.
#define GEMM_SMEM 73728   // 2*[128][36] A + 2*[128][36] B, uint32
template <bool BIAS, bool ACVT, bool OTF>
__global__ __launch_bounds__(256, 2)
void gemm_mma(const float* __restrict__ A, const float* __restrict__ Bt,
              const float* __restrict__ bias, float* __restrict__ C,
              int K, int Nout) {
    extern __shared__ char sm[];
    uint32_t* As = (uint32_t*)sm;               // [2][128][36]
    uint32_t* Bs = (uint32_t*)(sm + 36864);     // [2][128][36]
    const uint32_t sA = smem_u32(sm);
    const uint32_t sB = sA + 36864;

    const int tid = threadIdx.x, lane = tid & 31, warp = tid >> 5;
    const int g = lane >> 2, t = lane & 3;
    const int wm = warp >> 2, wn = warp & 3;
    const int mbase = blockIdx.y * 128, nbase = blockIdx.x * 128;

    const float* Ab = A + (size_t)mbase * K;
    const float* Bb = Bt + (size_t)nbase * K;

    int lr[4], lc[4];
#pragma unroll
    for (int i = 0; i < 4; i++) {
        int idx = tid + i * 256;
        lr[i] = idx >> 3;
        lc[i] = (idx & 7) << 2;
    }
    const int S = K >> 5;

    float4 rA[4];
    // prologue: stage 0
    if (ACVT) {
#pragma unroll
        for (int i = 0; i < 4; i++) rA[i] = *(const float4*)(Ab + (size_t)lr[i] * K + lc[i]);
    } else {
#pragma unroll
        for (int i = 0; i < 4; i++)
            cpa16(sA + (uint32_t)(lr[i] * 36 + lc[i]) * 4, Ab + (size_t)lr[i] * K + lc[i]);
    }
#pragma unroll
    for (int i = 0; i < 4; i++)
        cpa16(sB + (uint32_t)(lr[i] * 36 + lc[i]) * 4, Bb + (size_t)lr[i] * K + lc[i]);
    cp_commit();
    if (ACVT) {
#pragma unroll
        for (int i = 0; i < 4; i++)
            *(uint4*)&As[lr[i] * 36 + lc[i]] =
                make_uint4(f2tf(rA[i].x), f2tf(rA[i].y), f2tf(rA[i].z), f2tf(rA[i].w));
    }

    float cs[4][4][4];
#pragma unroll
    for (int i = 0; i < 4; i++)
#pragma unroll
        for (int j = 0; j < 4; j++)
#pragma unroll
            for (int q = 0; q < 4; q++) cs[i][j][q] = 0.f;

    for (int s = 0; s < S; s++) {
        const int nb = (s + 1) & 1;
        if (s + 1 < S) {
            const int k0 = (s + 1) << 5;
            if (ACVT) {
#pragma unroll
                for (int i = 0; i < 4; i++)
                    rA[i] = *(const float4*)(Ab + (size_t)lr[i] * K + k0 + lc[i]);
            } else {
#pragma unroll
                for (int i = 0; i < 4; i++)
                    cpa16(sA + (uint32_t)(nb * 4608 + lr[i] * 36 + lc[i]) * 4,
                          Ab + (size_t)lr[i] * K + k0 + lc[i]);
            }
#pragma unroll
            for (int i = 0; i < 4; i++)
                cpa16(sB + (uint32_t)(nb * 4608 + lr[i] * 36 + lc[i]) * 4,
                      Bb + (size_t)lr[i] * K + k0 + lc[i]);
            cp_commit();
            cp_wait<1>();
        } else {
            cp_wait<0>();
        }
        __syncthreads();

        const uint32_t* Ac = As + (s & 1) * 4608;
        const uint32_t* Bc = Bs + (s & 1) * 4608;
#pragma unroll
        for (int ks = 0; ks < 4; ks++) {
            const int kk = ks * 8 + t;
            uint32_t af[4][4], bf[4][2];
#pragma unroll
            for (int mt = 0; mt < 4; mt++) {
                int row = wm * 64 + mt * 16;
                af[mt][0] = Ac[(row + g) * 36 + kk];
                af[mt][1] = Ac[(row + g + 8) * 36 + kk];
                af[mt][2] = Ac[(row + g) * 36 + kk + 4];
                af[mt][3] = Ac[(row + g + 8) * 36 + kk + 4];
            }
#pragma unroll
            for (int nt = 0; nt < 4; nt++) {
                int rb = wn * 32 + nt * 8 + g;
                bf[nt][0] = Bc[rb * 36 + kk];
                bf[nt][1] = Bc[rb * 36 + kk + 4];
            }
#pragma unroll
            for (int mt = 0; mt < 4; mt++)
#pragma unroll
                for (int nt = 0; nt < 4; nt++) mma8(cs[mt][nt], af[mt], bf[nt]);
        }
        __syncthreads();
        if (ACVT && s + 1 < S) {
#pragma unroll
            for (int i = 0; i < 4; i++)
                *(uint4*)&As[nb * 4608 + lr[i] * 36 + lc[i]] =
                    make_uint4(f2tf(rA[i].x), f2tf(rA[i].y), f2tf(rA[i].z), f2tf(rA[i].w));
        }
    }

#pragma unroll
    for (int mt = 0; mt < 4; mt++) {
        int row = mbase + wm * 64 + mt * 16 + g;
#pragma unroll
        for (int nt = 0; nt < 4; nt++) {
            int col = nbase + wn * 32 + nt * 8 + 2 * t;
            float v0 = cs[mt][nt][0], v1 = cs[mt][nt][1];
            float v2 = cs[mt][nt][2], v3 = cs[mt][nt][3];
            if (BIAS) {
                float b0 = __ldg(bias + col), b1 = __ldg(bias + col + 1);
                v0 += b0; v1 += b1; v2 += b0; v3 += b1;
            }
            if (OTF) {
                *(float2*)(C + (size_t)row * Nout + col) =
                    make_float2(__uint_as_float(f2tf(v0)), __uint_as_float(f2tf(v1)));
                *(float2*)(C + (size_t)(row + 8) * Nout + col) =
                    make_float2(__uint_as_float(f2tf(v2)), __uint_as_float(f2tf(v3)));
            } else {
                *(float2*)(C + (size_t)row * Nout + col) = make_float2(v0, v1);
                *(float2*)(C + (size_t)(row + 8) * Nout + col) = make_float2(v2, v3);
            }
        }
    }
}

// ===== conv (4x4/stride4 im2col) pipelined GEMM, split-K=8 -> f32 partials =====
__global__ __launch_bounds__(256, 2)
void conv_mma(const float* __restrict__ x, const float* __restrict__ w2t,
              float* __restrict__ part) {
    extern __shared__ char sm[];
    uint32_t* As = (uint32_t*)sm;
    uint32_t* Bs = (uint32_t*)(sm + 36864);
    const uint32_t sB = smem_u32(sm) + 36864;

    const int tid = threadIdx.x, lane = tid & 31, warp = tid >> 5;
    const int g = lane >> 2, t = lane & 3;
    const int wm = warp >> 2, wn = warp & 3;
    const int mbase = blockIdx.y * 128, nbase = blockIdx.x * 128;
    const int kz = blockIdx.z;

    int lr[4], lc[4], rowb[4];
#pragma unroll
    for (int i = 0; i < 4; i++) {
        int idx = tid + i * 256;
        lr[i] = idx >> 3;
        lc[i] = (idx & 7) << 2;
        int m = mbase + lr[i];
        int b = m >> 8, p = m & 255;
        rowb[i] = b * 4096 + (p >> 4) * 256 + (p & 15) * 4;
    }

    auto ldA = [&](int s, float4* r) {
        int kg = kz * 512 + s * 32;
        int pix = kg >> 8, cin0 = kg & 255;
        int pi = pix >> 2, pj = pix & 3;
#pragma unroll
        for (int i = 0; i < 4; i++)
            r[i] = *(const float4*)(x + (size_t)(rowb[i] + pi * 64 + pj) * 256 + cin0 + lc[i]);
    };
    auto cpB = [&](int s, int buf) {
        int kg = kz * 512 + s * 32;
#pragma unroll
        for (int i = 0; i < 4; i++)
            cpa16(sB + (uint32_t)(buf * 4608 + lr[i] * 36 + lc[i]) * 4,
                  w2t + (size_t)(nbase + lr[i]) * 4096 + kg + lc[i]);
    };
    auto stA = [&](int buf, const float4* r) {
#pragma unroll
        for (int i = 0; i < 4; i++)
            *(uint4*)&As[buf * 4608 + lr[i] * 36 + lc[i]] =
                make_uint4(f2tf(r[i].x), f2tf(r[i].y), f2tf(r[i].z), f2tf(r[i].w));
    };

    float4 rA[4];
    ldA(0, rA);
    cpB(0, 0);
    cp_commit();
    stA(0, rA);

    float cs[4][4][4];
#pragma unroll
    for (int i = 0; i < 4; i++)
#pragma unroll
        for (int j = 0; j < 4; j++)
#pragma unroll
            for (int q = 0; q < 4; q++) cs[i][j][q] = 0.f;

    for (int s = 0; s < 16; s++) {
        const int nb = (s + 1) & 1;
        if (s + 1 < 16) {
            ldA(s + 1, rA);
            cpB(s + 1, nb);
            cp_commit();
            cp_wait<1>();
        } else {
            cp_wait<0>();
        }
        __syncthreads();
        const uint32_t* Ac = As + (s & 1) * 4608;
        const uint32_t* Bc = Bs + (s & 1) * 4608;
#pragma unroll
        for (int ks = 0; ks < 4; ks++) {
            const int kk = ks * 8 + t;
            uint32_t af[4][4], bf[4][2];
#pragma unroll
            for (int mt = 0; mt < 4; mt++) {
                int row = wm * 64 + mt * 16;
                af[mt][0] = Ac[(row + g) * 36 + kk];
                af[mt][1] = Ac[(row + g + 8) * 36 + kk];
                af[mt][2] = Ac[(row + g) * 36 + kk + 4];
                af[mt][3] = Ac[(row + g + 8) * 36 + kk + 4];
            }
#pragma unroll
            for (int nt = 0; nt < 4; nt++) {
                int rb = wn * 32 + nt * 8 + g;
                bf[nt][0] = Bc[rb * 36 + kk];
                bf[nt][1] = Bc[rb * 36 + kk + 4];
            }
#pragma unroll
            for (int mt = 0; mt < 4; mt++)
#pragma unroll
                for (int nt = 0; nt < 4; nt++) mma8(cs[mt][nt], af[mt], bf[nt]);
        }
        __syncthreads();
        if (s + 1 < 16) stA(nb, rA);
    }

    float* outp = part + (size_t)kz * 2048 * 256;
#pragma unroll
    for (int mt = 0; mt < 4; mt++) {
        int row = mbase + wm * 64 + mt * 16 + g;
#pragma unroll
        for (int nt = 0; nt < 4; nt++) {
            int col = nbase + wn * 32 + nt * 8 + 2 * t;
            *(float2*)(outp + (size_t)row * 256 + col) = make_float2(cs[mt][nt][0], cs[mt][nt][1]);
            *(float2*)(outp + (size_t)(row + 8) * 256 + col) = make_float2(cs[mt][nt][2], cs[mt][nt][3]);
        }
    }
}

// ===== split-K reduce + bias + LayerNorm, output tf32 bits =====
__global__ void reduce_ln(const float* __restrict__ part, const float* __restrict__ bias,
                          const float* __restrict__ w, const float* __restrict__ bvec,
                          float* __restrict__ xr) {
    __shared__ float red[18];
    const int r = blockIdx.x, c = threadIdx.x;
    float v = bias[c];
#pragma unroll
    for (int z = 0; z < SPLITK; z++)
        v += part[(size_t)z * 2048 * 256 + (size_t)r * 256 + c];
    float s1 = v, s2 = v * v;
#pragma unroll
    for (int off = 16; off; off >>= 1) {
        s1 += __shfl_xor_sync(~0u, s1, off);
        s2 += __shfl_xor_sync(~0u, s2, off);
    }
    int wid = c >> 5;
    if ((c & 31) == 0) { red[wid] = s1; red[8 + wid] = s2; }
    __syncthreads();
    if (c == 0) {
        float a = 0.f, q = 0.f;
#pragma unroll
        for (int i = 0; i < 8; i++) { a += red[i]; q += red[8 + i]; }
        red[16] = a; red[17] = q;
    }
    __syncthreads();
    float mu = red[16] * (1.0f / 256.0f);
    float var = red[17] * (1.0f / 256.0f) - mu * mu;
    float out = (v - mu) * rsqrtf(var + 1e-5f) * w[c] + bvec[c];
    xr[(size_t)r * 256 + c] = __uint_as_float(f2tf(out));
}

// ===== flash-style fused attention (mma.sync tf32, online softmax) =====
// grid (32, 8, 8), 256 thr = 8 warps, warp = 16 q-rows; 64-token chunks.
#define ATTN_SMEM 96256   // Ks[256][36] + Vs[256][40] + Pw[8][16][36] (uint32)
__global__ __launch_bounds__(256, 2)
void attn_mma(const float* __restrict__ q, const float* __restrict__ kvp,
              float* __restrict__ outp) {
    extern __shared__ uint32_t dsm[];
    uint32_t* Ks = dsm;                       // [256][36]
    uint32_t* Vs = dsm + 256 * 36;            // [256][40]
    uint32_t* Pw = dsm + 256 * 36 + 256 * 40 + (threadIdx.x >> 5) * 16 * 36;
    const uint32_t sKs = smem_u32(dsm);
    const uint32_t sVs = sKs + 256 * 36 * 4;

    const int tid = threadIdx.x, lane = tid & 31, warp = tid >> 5;
    const int g = lane >> 2, t = lane & 3;
    const int qt = blockIdx.x, h = blockIdx.y, b = blockIdx.z;
    const size_t qbase = (size_t)b * 4096 + (size_t)qt * 128;
    const int hoff = h * 32;

    // K,V tf32 bits via cp.async — FULL 32-col rows: 256 rows x 8 chunks each
    const float* kvhead = kvp + (size_t)b * 256 * 512 + hoff;
    for (int idx = tid; idx < 2048; idx += 256) {
        int tok = idx >> 3, c = (idx & 7) << 2;     // c ∈ {0,4,...,28}
        cpa16(sKs + (uint32_t)(tok * 36 + c) * 4, kvhead + (size_t)tok * 512 + c);
        cpa16(sVs + (uint32_t)(tok * 40 + c) * 4, kvhead + (size_t)tok * 512 + 256 + c);
    }
    cp_commit();

    // Q fragments (tf32 bits, plain LDG — overlaps with cp.async)
    const int qr = (int)qbase + warp * 16 + g;
    const uint32_t* qp = (const uint32_t*)q + (size_t)qr * 256 + hoff;
    uint32_t aq[4][4];
#pragma unroll
    for (int ks = 0; ks < 4; ks++) {
        aq[ks][0] = qp[ks * 8 + t];
        aq[ks][1] = qp[8 * 256 + ks * 8 + t];
        aq[ks][2] = qp[ks * 8 + t + 4];
        aq[ks][3] = qp[8 * 256 + ks * 8 + t + 4];
    }
    cp_wait<0>();
    __syncthreads();

    float m_lo = -1e30f, m_hi = -1e30f, l_lo = 0.f, l_hi = 0.f;
    float o[4][4];
#pragma unroll
    for (int nt = 0; nt < 4; nt++)
#pragma unroll
        for (int q2 = 0; q2 < 4; q2++) o[nt][q2] = 0.f;

#pragma unroll
    for (int ch = 0; ch < 4; ch++) {
        // S chunk = Q @ K[ch*64 .. ch*64+63]^T
        float s[8][4];
#pragma unroll
        for (int j = 0; j < 8; j++)
#pragma unroll
            for (int q2 = 0; q2 < 4; q2++) s[j][q2] = 0.f;
#pragma unroll
        for (int ks = 0; ks < 4; ks++) {
            const int kk = ks * 8 + t;
#pragma unroll
            for (int j = 0; j < 8; j++) {
                const uint32_t* kr = &Ks[(ch * 64 + j * 8 + g) * 36];
                uint32_t bf[2] = {kr[kk], kr[kk + 4]};
                mma8(s[j], aq[ks], bf);
            }
        }
        // online softmax update
        float cm_lo = s[0][0], cm_hi = s[0][2];
#pragma unroll
        for (int j = 0; j < 8; j++) {
            cm_lo = fmaxf(cm_lo, fmaxf(s[j][0], s[j][1]));
            cm_hi = fmaxf(cm_hi, fmaxf(s[j][2], s[j][3]));
        }
        cm_lo = fmaxf(cm_lo, __shfl_xor_sync(~0u, cm_lo, 1));
        cm_lo = fmaxf(cm_lo, __shfl_xor_sync(~0u, cm_lo, 2));
        cm_hi = fmaxf(cm_hi, __shfl_xor_sync(~0u, cm_hi, 1));
        cm_hi = fmaxf(cm_hi, __shfl_xor_sync(~0u, cm_hi, 2));
        float nm_lo = fmaxf(m_lo, cm_lo), nm_hi = fmaxf(m_hi, cm_hi);
        float sc_lo = ex2((m_lo - nm_lo) * ATT_C2);
        float sc_hi = ex2((m_hi - nm_hi) * ATT_C2);
        m_lo = nm_lo; m_hi = nm_hi;
        float ps_lo = 0.f, ps_hi = 0.f;
#pragma unroll
        for (int j = 0; j < 8; j++) {
            s[j][0] = ex2((s[j][0] - m_lo) * ATT_C2);
            s[j][1] = ex2((s[j][1] - m_lo) * ATT_C2);
            s[j][2] = ex2((s[j][2] - m_hi) * ATT_C2);
            s[j][3] = ex2((s[j][3] - m_hi) * ATT_C2);
            ps_lo += s[j][0] + s[j][1];
            ps_hi += s[j][2] + s[j][3];
        }
        l_lo = l_lo * sc_lo + ps_lo;
        l_hi = l_hi * sc_hi + ps_hi;
#pragma unroll
        for (int nt = 0; nt < 4; nt++) {
            o[nt][0] *= sc_lo; o[nt][1] *= sc_lo;
            o[nt][2] *= sc_hi; o[nt][3] *= sc_hi;
        }
        // O += P @ V  (two 32-token panels via warp-private SMEM)
#pragma unroll
        for (int p2 = 0; p2 < 2; p2++) {
#pragma unroll
            for (int jj = 0; jj < 4; jj++) {
                const int j = p2 * 4 + jj, pc = jj * 8;
                Pw[g * 36 + pc + 2 * t] = f2tf(s[j][0]);
                Pw[g * 36 + pc + 2 * t + 1] = f2tf(s[j][1]);
                Pw[(g + 8) * 36 + pc + 2 * t] = f2tf(s[j][2]);
                Pw[(g + 8) * 36 + pc + 2 * t + 1] = f2tf(s[j][3]);
            }
            __syncwarp();
#pragma unroll
            for (int ks = 0; ks < 4; ks++) {
                const int kk = ks * 8 + t;
                uint32_t ap[4] = {Pw[g * 36 + kk], Pw[(g + 8) * 36 + kk],
                                  Pw[g * 36 + kk + 4], Pw[(g + 8) * 36 + kk + 4]};
                const int tokb = ch * 64 + p2 * 32 + ks * 8;
#pragma unroll
                for (int nt = 0; nt < 4; nt++) {
                    uint32_t bf[2] = {Vs[(tokb + t) * 40 + nt * 8 + g],
                                      Vs[(tokb + t + 4) * 40 + nt * 8 + g]};
                    mma8(o[nt], ap, bf);
                }
            }
            __syncwarp();
        }
    }

    l_lo += __shfl_xor_sync(~0u, l_lo, 1);
    l_lo += __shfl_xor_sync(~0u, l_lo, 2);
    l_hi += __shfl_xor_sync(~0u, l_hi, 1);
    l_hi += __shfl_xor_sync(~0u, l_hi, 2);
    const float rlo = 1.0f / l_lo, rhi = 1.0f / l_hi;

    uint32_t* op = (uint32_t*)outp + (size_t)qr * 256 + hoff;
#pragma unroll
    for (int nt = 0; nt < 4; nt++) {
        op[nt * 8 + 2 * t] = f2tf(o[nt][0] * rlo);
        op[nt * 8 + 2 * t + 1] = f2tf(o[nt][1] * rlo);
        op[8 * 256 + nt * 8 + 2 * t] = f2tf(o[nt][2] * rhi);
        op[8 * 256 + nt * 8 + 2 * t + 1] = f2tf(o[nt][3] * rhi);
    }
}

// ---------------- launch ----------------
extern "C" void kernel_launch(void* const* d_in, const int* in_sizes, int n_in,
                              void* d_out, int out_size) {
    const float* ptrs[9] = {nullptr};
    int pi = 0;
    for (int i = 0; i < n_in && pi < 9; i++) {
        if (in_sizes[i] == 1) continue;  // H, W scalars
        ptrs[pi++] = (const float*)d_in[i];
    }
    const float* x      = ptrs[0];
    const float* q_w    = ptrs[1];
    const float* kv_w   = ptrs[2];
    const float* sr_w   = ptrs[3];
    const float* sr_b   = ptrs[4];
    const float* ln_w   = ptrs[5];
    const float* ln_b   = ptrs[6];
    const float* proj_w = ptrs[7];
    const float* proj_b = ptrs[8];
    float* out = (float*)d_out;

    float *pq, *pattn, *pxr, *pkv, *pw2t, *pqwT, *ppwT, *pkvwT, *ppart;
    cudaGetSymbolAddress((void**)&pq, g_q);
    cudaGetSymbolAddress((void**)&pattn, g_attn);
    cudaGetSymbolAddress((void**)&pxr, g_xr);
    cudaGetSymbolAddress((void**)&pkv, g_kv);
    cudaGetSymbolAddress((void**)&pw2t, g_w2t);
    cudaGetSymbolAddress((void**)&pqwT, g_qwT);
    cudaGetSymbolAddress((void**)&ppwT, g_pwT);
    cudaGetSymbolAddress((void**)&pkvwT, g_kvwT);
    cudaGetSymbolAddress((void**)&ppart, g_part);

    cudaFuncSetAttribute((const void*)gemm_mma<false, true, true>,
                         cudaFuncAttributeMaxDynamicSharedMemorySize, GEMM_SMEM);
    cudaFuncSetAttribute((const void*)gemm_mma<false, false, true>,
                         cudaFuncAttributeMaxDynamicSharedMemorySize, GEMM_SMEM);
    cudaFuncSetAttribute((const void*)gemm_mma<true, false, false>,
                         cudaFuncAttributeMaxDynamicSharedMemorySize, GEMM_SMEM);
    cudaFuncSetAttribute((const void*)conv_mma,
                         cudaFuncAttributeMaxDynamicSharedMemorySize, GEMM_SMEM);
    cudaFuncSetAttribute((const void*)attn_mma,
                         cudaFuncAttributeMaxDynamicSharedMemorySize, ATTN_SMEM);

    // fused weight prep (tf32 bits)
    prep_all<<<5120, 256>>>(q_w, proj_w, kv_w, sr_w, pqwT, ppwT, pkvwT, pw2t);
    // q = x @ q_w  -> tf32 bits
    gemm_mma<false, true, true><<<dim3(2, 256), 256, GEMM_SMEM>>>(x, pqwT, nullptr, pq, 256, 256);
    // conv partials (split-K=8), f32
    conv_mma<<<dim3(2, 16, SPLITK), 256, GEMM_SMEM>>>(x, pw2t, ppart);
    // reduce + bias + LN -> tf32 bits
    reduce_ln<<<2048, 256>>>(ppart, sr_b, ln_w, ln_b, pxr);
    // kv = xr @ kv_w -> tf32 bits
    gemm_mma<false, false, true><<<dim3(4, 16), 256, GEMM_SMEM>>>(pxr, pkvwT, nullptr, pkv, 256, 512);
    // flash attention -> tf32 bits
    attn_mma<<<dim3(32, 8, 8), 256, ATTN_SMEM>>>(pq, pkv, pattn);
    // out = attn @ proj_w + proj_b (f32)
    gemm_mma<true, false, false><<<dim3(2, 256), 256, GEMM_SMEM>>>(pattn, ppwT, proj_b, out, 256, 256);
}

// round 6
// speedup vs baseline: 5.6221x; 1.5072x over previous
#include <cuda_runtime.h>
#include <cuda_fp16.h>
#include <cstdint>

#define ATT_C2 0.25506238539520833f   // (1/sqrt(32)) * log2(e)
#define SPLITK 8

// ---------------- scratch (no allocation allowed) ----------------
__device__ __half g_q   [8 * 4096 * 256];   // q (fp16)
__device__ __half g_attn[8 * 4096 * 256];   // attention out (fp16)
__device__ __half g_xr  [2048 * 256];       // LN out (fp16)
__device__ __half g_k   [2048 * 256];       // K tokens (fp16) [b*256+tok][256]
__device__ __half g_vt  [64 * 32 * 256];    // V^T (fp16) [(b*8+h)*32+d][tok]
__device__ __half g_qwT [256 * 256];
__device__ __half g_pwT [256 * 256];
__device__ __half g_kvwT[512 * 256];
__device__ __half g_w2t [256 * 4096];       // conv weights [co][pix*256+cin]
__device__ float  g_part[SPLITK * 2048 * 256];

// ================= helpers =================
__device__ __forceinline__ uint32_t pk2(float a, float b) {
    __half2 h = __floats2half2_rn(a, b);
    return *reinterpret_cast<uint32_t*>(&h);
}
__device__ __forceinline__ float ex2(float x) {
    float y;
    asm("ex2.approx.f32 %0, %1;" : "=f"(y) : "f"(x));
    return y;
}
__device__ __forceinline__ uint32_t smem_u32(const void* p) {
    uint32_t a;
    asm("{ .reg .u64 t; cvta.to.shared.u64 t, %1; cvt.u32.u64 %0, t; }" : "=r"(a) : "l"(p));
    return a;
}
__device__ __forceinline__ void cpa16(uint32_t d, const void* s) {
    asm volatile("cp.async.ca.shared.global [%0], [%1], 16;" :: "r"(d), "l"(s) : "memory");
}
__device__ __forceinline__ void cp_commit() {
    asm volatile("cp.async.commit_group;" ::: "memory");
}
template <int N>
__device__ __forceinline__ void cp_wait() {
    asm volatile("cp.async.wait_group %0;" :: "n"(N) : "memory");
}
// D += A@B  (m16n8k16 fp16 in, fp32 acc)
__device__ __forceinline__ void mma16(float* d, const uint32_t* a, const uint32_t* b) {
    asm volatile(
        "mma.sync.aligned.m16n8k16.row.col.f32.f16.f16.f32 "
        "{%0,%1,%2,%3}, {%4,%5,%6,%7}, {%8,%9}, {%0,%1,%2,%3};"
        : "+f"(d[0]), "+f"(d[1]), "+f"(d[2]), "+f"(d[3])
        : "r"(a[0]), "r"(a[1]), "r"(a[2]), "r"(a[3]), "r"(b[0]), "r"(b[1]));
}

// ===== fused weight prep: transposes + relayout, fp16 out =====
__global__ void prep_all(const float* __restrict__ qw, const float* __restrict__ pw,
                         const float* __restrict__ kvw, const float* __restrict__ srw,
                         __half* __restrict__ qwT, __half* __restrict__ pwT,
                         __half* __restrict__ kvwT, __half* __restrict__ w2t) {
    int t = blockIdx.x * 256 + threadIdx.x;
    if (t < 65536) {
        int n = t >> 8, k = t & 255;
        qwT[t] = __float2half_rn(qw[k * 256 + n]);
    } else if (t < 131072) {
        int u = t - 65536;
        int n = u >> 8, k = u & 255;
        pwT[u] = __float2half_rn(pw[k * 256 + n]);
    } else if (t < 262144) {
        int u = t - 131072;
        int n = u >> 8, k = u & 255;
        kvwT[u] = __float2half_rn(kvw[k * 512 + n]);
    } else {
        int u = t - 262144;  // < 1048576
        int co = u >> 12, rem = u & 4095;
        int pix = rem >> 8, cin = rem & 255;
        w2t[u] = __float2half_rn(srw[co * 4096 + cin * 16 + pix]);
    }
}

// ===== pipelined fp16 GEMM: C[M,Nout] = A[M,K] @ Bt[Nout,K]^T =====
// CTA 128x128, BK=32, 256 thr = 8 warps (2M x 4N). 2-stage cp.async pipeline.
// MODE 0: f32 out + bias (proj).  MODE 1: fp16 out.  MODE 2: kv split (K rows + V^T).
// ACVT: A is f32, convert to fp16 on SMEM store; else A already fp16 (cp.async).
template <int MODE, bool ACVT>
__global__ __launch_bounds__(256, 2)
void gemm_h(const void* __restrict__ Ap, const __half* __restrict__ Bt,
            const float* __restrict__ bias, void* __restrict__ Cp,
            __half* __restrict__ C2, int K, int Nout) {
    __shared__ uint32_t As[2][128][20];   // 16 half2 used + pad
    __shared__ uint32_t Bs[2][128][20];

    const int tid = threadIdx.x, lane = tid & 31, warp = tid >> 5;
    const int g = lane >> 2, t = lane & 3;
    const int wm = warp >> 2, wn = warp & 3;
    const int mbase = blockIdx.y * 128, nbase = blockIdx.x * 128;

    const float*  Af = (const float*)Ap + (size_t)mbase * K;
    const __half* Ah = (const __half*)Ap + (size_t)mbase * K;
    const __half* Bh = Bt + (size_t)nbase * K;

    // half cp.async mapping: 2 chunks/thread (128 rows x 4 x 16B)
    int hr[2], hcu[2];
#pragma unroll
    for (int i = 0; i < 2; i++) {
        int idx = tid + i * 256;
        hr[i] = idx >> 2;
        hcu[i] = (idx & 3) << 2;
    }
    // f32 A mapping: 4 float4/thread
    int lr[4], lc[4];
#pragma unroll
    for (int i = 0; i < 4; i++) {
        int idx = tid + i * 256;
        lr[i] = idx >> 3;
        lc[i] = (idx & 7) << 2;
    }
    const int S = K >> 5;

    float4 rA[4];
    if (ACVT) {
#pragma unroll
        for (int i = 0; i < 4; i++) rA[i] = *(const float4*)(Af + (size_t)lr[i] * K + lc[i]);
    } else {
#pragma unroll
        for (int i = 0; i < 2; i++)
            cpa16(smem_u32(&As[0][hr[i]][hcu[i]]), Ah + (size_t)hr[i] * K + hcu[i] * 2);
    }
#pragma unroll
    for (int i = 0; i < 2; i++)
        cpa16(smem_u32(&Bs[0][hr[i]][hcu[i]]), Bh + (size_t)hr[i] * K + hcu[i] * 2);
    cp_commit();
    if (ACVT) {
#pragma unroll
        for (int i = 0; i < 4; i++)
            *(uint2*)&As[0][lr[i]][lc[i] >> 1] =
                make_uint2(pk2(rA[i].x, rA[i].y), pk2(rA[i].z, rA[i].w));
    }

    float cs[4][4][4];
#pragma unroll
    for (int i = 0; i < 4; i++)
#pragma unroll
        for (int j = 0; j < 4; j++)
#pragma unroll
            for (int q = 0; q < 4; q++) cs[i][j][q] = 0.f;

    for (int s = 0; s < S; s++) {
        const int cb = s & 1, nb = (s + 1) & 1;
        if (s + 1 < S) {
            const int k0 = (s + 1) << 5;
            if (ACVT) {
#pragma unroll
                for (int i = 0; i < 4; i++)
                    rA[i] = *(const float4*)(Af + (size_t)lr[i] * K + k0 + lc[i]);
            } else {
#pragma unroll
                for (int i = 0; i < 2; i++)
                    cpa16(smem_u32(&As[nb][hr[i]][hcu[i]]),
                          Ah + (size_t)hr[i] * K + k0 + hcu[i] * 2);
            }
#pragma unroll
            for (int i = 0; i < 2; i++)
                cpa16(smem_u32(&Bs[nb][hr[i]][hcu[i]]),
                      Bh + (size_t)hr[i] * K + k0 + hcu[i] * 2);
            cp_commit();
            cp_wait<1>();
        } else {
            cp_wait<0>();
        }
        __syncthreads();

#pragma unroll
        for (int ks = 0; ks < 2; ks++) {
            const int kk = ks * 8 + t;
            uint32_t af[4][4], bf[4][2];
#pragma unroll
            for (int mt = 0; mt < 4; mt++) {
                int row = wm * 64 + mt * 16;
                af[mt][0] = As[cb][row + g][kk];
                af[mt][1] = As[cb][row + g + 8][kk];
                af[mt][2] = As[cb][row + g][kk + 4];
                af[mt][3] = As[cb][row + g + 8][kk + 4];
            }
#pragma unroll
            for (int nt = 0; nt < 4; nt++) {
                int rb = wn * 32 + nt * 8 + g;
                bf[nt][0] = Bs[cb][rb][kk];
                bf[nt][1] = Bs[cb][rb][kk + 4];
            }
#pragma unroll
            for (int mt = 0; mt < 4; mt++)
#pragma unroll
                for (int nt = 0; nt < 4; nt++) mma16(cs[mt][nt], af[mt], bf[nt]);
        }
        __syncthreads();
        if (ACVT && s + 1 < S) {
#pragma unroll
            for (int i = 0; i < 4; i++)
                *(uint2*)&As[nb][lr[i]][lc[i] >> 1] =
                    make_uint2(pk2(rA[i].x, rA[i].y), pk2(rA[i].z, rA[i].w));
        }
    }

#pragma unroll
    for (int mt = 0; mt < 4; mt++) {
        int row0 = mbase + wm * 64 + mt * 16 + g;
#pragma unroll
        for (int nt = 0; nt < 4; nt++) {
            int col = nbase + wn * 32 + nt * 8 + 2 * t;
            float v0 = cs[mt][nt][0], v1 = cs[mt][nt][1];
            float v2 = cs[mt][nt][2], v3 = cs[mt][nt][3];
            if (MODE == 0) {
                float b0 = __ldg(bias + col), b1 = __ldg(bias + col + 1);
                float* C = (float*)Cp;
                *(float2*)(C + (size_t)row0 * Nout + col) = make_float2(v0 + b0, v1 + b1);
                *(float2*)(C + (size_t)(row0 + 8) * Nout + col) = make_float2(v2 + b0, v3 + b1);
            } else if (MODE == 1) {
                uint32_t* C = (uint32_t*)Cp;
                C[((size_t)row0 * Nout + col) >> 1] = pk2(v0, v1);
                C[((size_t)(row0 + 8) * Nout + col) >> 1] = pk2(v2, v3);
            } else {
                // kv split: rows are (b*256+tok); col<256 -> K, else V^T
                if (col < 256) {
                    uint32_t* C = (uint32_t*)Cp;
                    C[((size_t)row0 * 256 + col) >> 1] = pk2(v0, v1);
                    C[((size_t)(row0 + 8) * 256 + col) >> 1] = pk2(v2, v3);
                } else {
                    int dim = col - 256;
                    int h = dim >> 5, d = dim & 31;
                    int b0i = row0 >> 8, tok0 = row0 & 255;
                    size_t rbase = (size_t)((b0i * 8 + h) * 32 + d) * 256;
                    C2[rbase + tok0] = __float2half_rn(v0);
                    C2[rbase + 256 + tok0] = __float2half_rn(v1);
                    C2[rbase + tok0 + 8] = __float2half_rn(v2);
                    C2[rbase + 256 + tok0 + 8] = __float2half_rn(v3);
                }
            }
        }
    }
}

// ===== conv (4x4/stride4 im2col) fp16 GEMM, split-K=8 -> f32 partials =====
__global__ __launch_bounds__(256, 2)
void conv_h(const float* __restrict__ x, const __half* __restrict__ w2t,
            float* __restrict__ part) {
    __shared__ uint32_t As[2][128][20];
    __shared__ uint32_t Bs[2][128][20];

    const int tid = threadIdx.x, lane = tid & 31, warp = tid >> 5;
    const int g = lane >> 2, t = lane & 3;
    const int wm = warp >> 2, wn = warp & 3;
    const int mbase = blockIdx.y * 128, nbase = blockIdx.x * 128;
    const int kz = blockIdx.z;

    int hr[2], hcu[2];
#pragma unroll
    for (int i = 0; i < 2; i++) {
        int idx = tid + i * 256;
        hr[i] = idx >> 2;
        hcu[i] = (idx & 3) << 2;
    }
    int lr[4], lc[4], rowb[4];
#pragma unroll
    for (int i = 0; i < 4; i++) {
        int idx = tid + i * 256;
        lr[i] = idx >> 3;
        lc[i] = (idx & 7) << 2;
        int m = mbase + lr[i];
        int b = m >> 8, p = m & 255;
        rowb[i] = b * 4096 + (p >> 4) * 256 + (p & 15) * 4;
    }

    auto ldA = [&](int s, float4* r) {
        int kg = kz * 512 + s * 32;
        int pix = kg >> 8, cin0 = kg & 255;
        int pi = pix >> 2, pj = pix & 3;
#pragma unroll
        for (int i = 0; i < 4; i++)
            r[i] = *(const float4*)(x + (size_t)(rowb[i] + pi * 64 + pj) * 256 + cin0 + lc[i]);
    };
    auto cpB = [&](int s, int buf) {
        int kg = kz * 512 + s * 32;
#pragma unroll
        for (int i = 0; i < 2; i++)
            cpa16(smem_u32(&Bs[buf][hr[i]][hcu[i]]),
                  w2t + (size_t)(nbase + hr[i]) * 4096 + kg + hcu[i] * 2);
    };
    auto stA = [&](int buf, const float4* r) {
#pragma unroll
        for (int i = 0; i < 4; i++)
            *(uint2*)&As[buf][lr[i]][lc[i] >> 1] =
                make_uint2(pk2(r[i].x, r[i].y), pk2(r[i].z, r[i].w));
    };

    float4 rA[4];
    ldA(0, rA);
    cpB(0, 0);
    cp_commit();
    stA(0, rA);

    float cs[4][4][4];
#pragma unroll
    for (int i = 0; i < 4; i++)
#pragma unroll
        for (int j = 0; j < 4; j++)
#pragma unroll
            for (int q = 0; q < 4; q++) cs[i][j][q] = 0.f;

    for (int s = 0; s < 16; s++) {
        const int cb = s & 1, nb = (s + 1) & 1;
        if (s + 1 < 16) {
            ldA(s + 1, rA);
            cpB(s + 1, nb);
            cp_commit();
            cp_wait<1>();
        } else {
            cp_wait<0>();
        }
        __syncthreads();
#pragma unroll
        for (int ks = 0; ks < 2; ks++) {
            const int kk = ks * 8 + t;
            uint32_t af[4][4], bf[4][2];
#pragma unroll
            for (int mt = 0; mt < 4; mt++) {
                int row = wm * 64 + mt * 16;
                af[mt][0] = As[cb][row + g][kk];
                af[mt][1] = As[cb][row + g + 8][kk];
                af[mt][2] = As[cb][row + g][kk + 4];
                af[mt][3] = As[cb][row + g + 8][kk + 4];
            }
#pragma unroll
            for (int nt = 0; nt < 4; nt++) {
                int rb = wn * 32 + nt * 8 + g;
                bf[nt][0] = Bs[cb][rb][kk];
                bf[nt][1] = Bs[cb][rb][kk + 4];
            }
#pragma unroll
            for (int mt = 0; mt < 4; mt++)
#pragma unroll
                for (int nt = 0; nt < 4; nt++) mma16(cs[mt][nt], af[mt], bf[nt]);
        }
        __syncthreads();
        if (s + 1 < 16) stA(nb, rA);
    }

    float* outp = part + (size_t)kz * 2048 * 256;
#pragma unroll
    for (int mt = 0; mt < 4; mt++) {
        int row = mbase + wm * 64 + mt * 16 + g;
#pragma unroll
        for (int nt = 0; nt < 4; nt++) {
            int col = nbase + wn * 32 + nt * 8 + 2 * t;
            *(float2*)(outp + (size_t)row * 256 + col) = make_float2(cs[mt][nt][0], cs[mt][nt][1]);
            *(float2*)(outp + (size_t)(row + 8) * 256 + col) = make_float2(cs[mt][nt][2], cs[mt][nt][3]);
        }
    }
}

// ===== split-K reduce + bias + LayerNorm -> fp16 =====
__global__ void reduce_ln(const float* __restrict__ part, const float* __restrict__ bias,
                          const float* __restrict__ w, const float* __restrict__ bvec,
                          __half* __restrict__ xr) {
    __shared__ float red[18];
    const int r = blockIdx.x, c = threadIdx.x;
    float v = bias[c];
#pragma unroll
    for (int z = 0; z < SPLITK; z++)
        v += part[(size_t)z * 2048 * 256 + (size_t)r * 256 + c];
    float s1 = v, s2 = v * v;
#pragma unroll
    for (int off = 16; off; off >>= 1) {
        s1 += __shfl_xor_sync(~0u, s1, off);
        s2 += __shfl_xor_sync(~0u, s2, off);
    }
    int wid = c >> 5;
    if ((c & 31) == 0) { red[wid] = s1; red[8 + wid] = s2; }
    __syncthreads();
    if (c == 0) {
        float a = 0.f, q = 0.f;
#pragma unroll
        for (int i = 0; i < 8; i++) { a += red[i]; q += red[8 + i]; }
        red[16] = a; red[17] = q;
    }
    __syncthreads();
    float mu = red[16] * (1.0f / 256.0f);
    float var = red[17] * (1.0f / 256.0f) - mu * mu;
    float out = (v - mu) * rsqrtf(var + 1e-5f) * w[c] + bvec[c];
    xr[(size_t)r * 256 + c] = __float2half_rn(out);
}

// ===== flash fused attention, fp16 mma (m16n8k16), online softmax =====
// grid (32, 8, 8), 256 thr = 8 warps, warp = 16 q-rows, 64-token chunks.
__global__ __launch_bounds__(256)
void attn_h(const __half* __restrict__ qh, const __half* __restrict__ kh,
            const __half* __restrict__ vth, __half* __restrict__ outp) {
    __shared__ uint32_t Ks[256][20];    // K tokens, 16 half2 + pad
    __shared__ uint32_t VsT[32][132];   // V^T [dim][tok/2], 128 half2 + pad
    __shared__ uint32_t Pw8[8][16][20]; // per-warp P panels

    const int tid = threadIdx.x, lane = tid & 31, warp = tid >> 5;
    const int g = lane >> 2, t = lane & 3;
    const int qt = blockIdx.x, h = blockIdx.y, b = blockIdx.z;
    const size_t qbase = (size_t)b * 4096 + (size_t)qt * 128;
    const int hoff = h * 32;
    uint32_t (*Pw)[20] = Pw8[warp];

    // K (token-major) + V^T loads via cp.async
    const __half* kbase = kh + (size_t)b * 256 * 256 + hoff;
    const __half* vbase = vth + (size_t)((b * 8 + h) * 32) * 256;
    for (int idx = tid; idx < 2048; idx += 256) {
        if (idx < 1024) {
            int tok = idx >> 2, cu = (idx & 3) << 2;
            cpa16(smem_u32(&Ks[tok][cu]), kbase + (size_t)tok * 256 + cu * 2);
        } else {
            int u = idx - 1024;
            int d = u >> 5, cu = (u & 31) << 2;
            cpa16(smem_u32(&VsT[d][cu]), vbase + (size_t)d * 256 + cu * 2);
        }
    }
    cp_commit();

    // Q fragments (fp16 bits, u32 reads)
    const int qr = (int)qbase + warp * 16 + g;
    const uint32_t* qp = (const uint32_t*)qh + (size_t)qr * 128 + (hoff >> 1);
    uint32_t aq[2][4];
#pragma unroll
    for (int ks = 0; ks < 2; ks++) {
        aq[ks][0] = qp[ks * 8 + t];
        aq[ks][1] = qp[8 * 128 + ks * 8 + t];
        aq[ks][2] = qp[ks * 8 + t + 4];
        aq[ks][3] = qp[8 * 128 + ks * 8 + t + 4];
    }
    cp_wait<0>();
    __syncthreads();

    float m_lo = -1e30f, m_hi = -1e30f, l_lo = 0.f, l_hi = 0.f;
    float o[4][4];
#pragma unroll
    for (int nt = 0; nt < 4; nt++)
#pragma unroll
        for (int q2 = 0; q2 < 4; q2++) o[nt][q2] = 0.f;

#pragma unroll
    for (int ch = 0; ch < 4; ch++) {
        float s[8][4];
#pragma unroll
        for (int j = 0; j < 8; j++)
#pragma unroll
            for (int q2 = 0; q2 < 4; q2++) s[j][q2] = 0.f;
#pragma unroll
        for (int ks = 0; ks < 2; ks++) {
            const int kk = ks * 8 + t;
#pragma unroll
            for (int j = 0; j < 8; j++) {
                const uint32_t* kr = Ks[ch * 64 + j * 8 + g];
                uint32_t bf[2] = {kr[kk], kr[kk + 4]};
                mma16(s[j], aq[ks], bf);
            }
        }
        // online softmax
        float cm_lo = s[0][0], cm_hi = s[0][2];
#pragma unroll
        for (int j = 0; j < 8; j++) {
            cm_lo = fmaxf(cm_lo, fmaxf(s[j][0], s[j][1]));
            cm_hi = fmaxf(cm_hi, fmaxf(s[j][2], s[j][3]));
        }
        cm_lo = fmaxf(cm_lo, __shfl_xor_sync(~0u, cm_lo, 1));
        cm_lo = fmaxf(cm_lo, __shfl_xor_sync(~0u, cm_lo, 2));
        cm_hi = fmaxf(cm_hi, __shfl_xor_sync(~0u, cm_hi, 1));
        cm_hi = fmaxf(cm_hi, __shfl_xor_sync(~0u, cm_hi, 2));
        float nm_lo = fmaxf(m_lo, cm_lo), nm_hi = fmaxf(m_hi, cm_hi);
        float sc_lo = ex2((m_lo - nm_lo) * ATT_C2);
        float sc_hi = ex2((m_hi - nm_hi) * ATT_C2);
        m_lo = nm_lo; m_hi = nm_hi;
        float ps_lo = 0.f, ps_hi = 0.f;
#pragma unroll
        for (int j = 0; j < 8; j++) {
            s[j][0] = ex2((s[j][0] - m_lo) * ATT_C2);
            s[j][1] = ex2((s[j][1] - m_lo) * ATT_C2);
            s[j][2] = ex2((s[j][2] - m_hi) * ATT_C2);
            s[j][3] = ex2((s[j][3] - m_hi) * ATT_C2);
            ps_lo += s[j][0] + s[j][1];
            ps_hi += s[j][2] + s[j][3];
        }
        l_lo = l_lo * sc_lo + ps_lo;
        l_hi = l_hi * sc_hi + ps_hi;
#pragma unroll
        for (int nt = 0; nt < 4; nt++) {
            o[nt][0] *= sc_lo; o[nt][1] *= sc_lo;
            o[nt][2] *= sc_hi; o[nt][3] *= sc_hi;
        }
        // O += P @ V : two 32-token panels
#pragma unroll
        for (int p2 = 0; p2 < 2; p2++) {
#pragma unroll
            for (int jj = 0; jj < 4; jj++) {
                const int j = p2 * 4 + jj;
                Pw[g][jj * 4 + t] = pk2(s[j][0], s[j][1]);
                Pw[g + 8][jj * 4 + t] = pk2(s[j][2], s[j][3]);
            }
            __syncwarp();
#pragma unroll
            for (int ks = 0; ks < 2; ks++) {
                uint32_t ap[4] = {Pw[g][ks * 8 + t], Pw[g + 8][ks * 8 + t],
                                  Pw[g][ks * 8 + t + 4], Pw[g + 8][ks * 8 + t + 4]};
                const int tu = (ch * 64 + p2 * 32 + ks * 16) >> 1;  // u32 token index
#pragma unroll
                for (int nt = 0; nt < 4; nt++) {
                    const uint32_t* vr = VsT[nt * 8 + g];
                    uint32_t bf[2] = {vr[tu + t], vr[tu + 4 + t]};
                    mma16(o[nt], ap, bf);
                }
            }
            __syncwarp();
        }
    }

    l_lo += __shfl_xor_sync(~0u, l_lo, 1);
    l_lo += __shfl_xor_sync(~0u, l_lo, 2);
    l_hi += __shfl_xor_sync(~0u, l_hi, 1);
    l_hi += __shfl_xor_sync(~0u, l_hi, 2);
    const float rlo = 1.0f / l_lo, rhi = 1.0f / l_hi;

    uint32_t* op = (uint32_t*)outp + (size_t)qr * 128 + (hoff >> 1);
#pragma unroll
    for (int nt = 0; nt < 4; nt++) {
        op[nt * 4 + t] = pk2(o[nt][0] * rlo, o[nt][1] * rlo);
        op[8 * 128 + nt * 4 + t] = pk2(o[nt][2] * rhi, o[nt][3] * rhi);
    }
}

// ---------------- launch ----------------
extern "C" void kernel_launch(void* const* d_in, const int* in_sizes, int n_in,
                              void* d_out, int out_size) {
    const float* ptrs[9] = {nullptr};
    int pi = 0;
    for (int i = 0; i < n_in && pi < 9; i++) {
        if (in_sizes[i] == 1) continue;  // H, W scalars
        ptrs[pi++] = (const float*)d_in[i];
    }
    const float* x      = ptrs[0];
    const float* q_w    = ptrs[1];
    const float* kv_w   = ptrs[2];
    const float* sr_w   = ptrs[3];
    const float* sr_b   = ptrs[4];
    const float* ln_w   = ptrs[5];
    const float* ln_b   = ptrs[6];
    const float* proj_w = ptrs[7];
    const float* proj_b = ptrs[8];
    float* out = (float*)d_out;

    __half *pq, *pattn, *pxr, *pk, *pvt, *pqwT, *ppwT, *pkvwT, *pw2t;
    float* ppart;
    cudaGetSymbolAddress((void**)&pq, g_q);
    cudaGetSymbolAddress((void**)&pattn, g_attn);
    cudaGetSymbolAddress((void**)&pxr, g_xr);
    cudaGetSymbolAddress((void**)&pk, g_k);
    cudaGetSymbolAddress((void**)&pvt, g_vt);
    cudaGetSymbolAddress((void**)&pqwT, g_qwT);
    cudaGetSymbolAddress((void**)&ppwT, g_pwT);
    cudaGetSymbolAddress((void**)&pkvwT, g_kvwT);
    cudaGetSymbolAddress((void**)&pw2t, g_w2t);
    cudaGetSymbolAddress((void**)&ppart, g_part);

    // fused weight prep -> fp16
    prep_all<<<5120, 256>>>(q_w, proj_w, kv_w, sr_w, pqwT, ppwT, pkvwT, pw2t);
    // q = x @ q_w -> fp16
    gemm_h<1, true><<<dim3(2, 256), 256>>>(x, pqwT, nullptr, pq, nullptr, 256, 256);
    // conv partials (split-K=8), f32
    conv_h<<<dim3(2, 16, SPLITK), 256>>>(x, pw2t, ppart);
    // reduce + bias + LN -> fp16
    reduce_ln<<<2048, 256>>>(ppart, sr_b, ln_w, ln_b, pxr);
    // kv = xr @ kv_w -> K rows (fp16) + V^T (fp16)
    gemm_h<2, false><<<dim3(4, 16), 256>>>(pxr, pkvwT, nullptr, pk, pvt, 256, 512);
    // flash attention -> fp16
    attn_h<<<dim3(32, 8, 8), 256>>>(pq, pk, pvt, pattn);
    // out = attn @ proj_w + proj_b (f32)
    gemm_h<0, false><<<dim3(2, 256), 256>>>(pattn, ppwT, proj_b, out, nullptr, 256, 256);
}

// round 7
// speedup vs baseline: 5.8064x; 1.0328x over previous
#include <cuda_runtime.h>
#include <cuda_fp16.h>
#include <cstdint>

#define ATT_C2 0.25506238539520833f   // (1/sqrt(32)) * log2(e)
#define SPLITK 8

// ---------------- scratch (no allocation allowed) ----------------
__device__ __half g_q   [8 * 4096 * 256];   // q (fp16)
__device__ __half g_attn[8 * 4096 * 256];   // attention out (fp16)
__device__ __half g_xr  [2048 * 256];       // LN out (fp16)
__device__ __half g_k   [2048 * 256];       // K tokens (fp16) [b*256+tok][256]
__device__ __half g_vt  [64 * 32 * 256];    // V^T (fp16) [(b*8+h)*32+d][tok]
__device__ __half g_qwT [256 * 256];
__device__ __half g_pwT [256 * 256];
__device__ __half g_kvwT[512 * 256];
__device__ __half g_w2t [256 * 4096];       // conv weights [co][pix*256+cin]
__device__ float  g_part[SPLITK * 2048 * 256];

// ================= helpers =================
__device__ __forceinline__ uint32_t pk2(float a, float b) {
    __half2 h = __floats2half2_rn(a, b);
    return *reinterpret_cast<uint32_t*>(&h);
}
__device__ __forceinline__ float ex2(float x) {
    float y;
    asm("ex2.approx.f32 %0, %1;" : "=f"(y) : "f"(x));
    return y;
}
__device__ __forceinline__ uint32_t smem_u32(const void* p) {
    uint32_t a;
    asm("{ .reg .u64 t; cvta.to.shared.u64 t, %1; cvt.u32.u64 %0, t; }" : "=r"(a) : "l"(p));
    return a;
}
__device__ __forceinline__ void cpa16(uint32_t d, const void* s) {
    asm volatile("cp.async.ca.shared.global [%0], [%1], 16;" :: "r"(d), "l"(s) : "memory");
}
__device__ __forceinline__ void cp_commit() {
    asm volatile("cp.async.commit_group;" ::: "memory");
}
template <int N>
__device__ __forceinline__ void cp_wait() {
    asm volatile("cp.async.wait_group %0;" :: "n"(N) : "memory");
}
// D += A@B  (m16n8k16 fp16 in, fp32 acc)
__device__ __forceinline__ void mma16(float* d, const uint32_t* a, const uint32_t* b) {
    asm volatile(
        "mma.sync.aligned.m16n8k16.row.col.f32.f16.f16.f32 "
        "{%0,%1,%2,%3}, {%4,%5,%6,%7}, {%8,%9}, {%0,%1,%2,%3};"
        : "+f"(d[0]), "+f"(d[1]), "+f"(d[2]), "+f"(d[3])
        : "r"(a[0]), "r"(a[1]), "r"(a[2]), "r"(a[3]), "r"(b[0]), "r"(b[1]));
}

typedef uint32_t Tile[128][20];

// ===== fused weight prep: transposes + relayout, fp16 out =====
__global__ void prep_all(const float* __restrict__ qw, const float* __restrict__ pw,
                         const float* __restrict__ kvw, const float* __restrict__ srw,
                         __half* __restrict__ qwT, __half* __restrict__ pwT,
                         __half* __restrict__ kvwT, __half* __restrict__ w2t) {
    int t = blockIdx.x * 256 + threadIdx.x;
    if (t < 65536) {
        int n = t >> 8, k = t & 255;
        qwT[t] = __float2half_rn(qw[k * 256 + n]);
    } else if (t < 131072) {
        int u = t - 65536;
        int n = u >> 8, k = u & 255;
        pwT[u] = __float2half_rn(pw[k * 256 + n]);
    } else if (t < 262144) {
        int u = t - 131072;
        int n = u >> 8, k = u & 255;
        kvwT[u] = __float2half_rn(kvw[k * 512 + n]);
    } else {
        int u = t - 262144;  // < 1048576
        int co = u >> 12, rem = u & 4095;
        int pix = rem >> 8, cin = rem & 255;
        w2t[u] = __float2half_rn(srw[co * 4096 + cin * 16 + pix]);
    }
}

// ===== q-GEMM body: pq[M,256] = fp16(x[M,256] @ qwT^T), A f32 cvt =====
__device__ void q_body(Tile* As, Tile* Bs, const float* __restrict__ x,
                       const __half* __restrict__ qwT, __half* __restrict__ pq,
                       int bx, int by) {
    const int K = 256, Nout = 256;
    const int tid = threadIdx.x, lane = tid & 31, warp = tid >> 5;
    const int g = lane >> 2, t = lane & 3;
    const int wm = warp >> 2, wn = warp & 3;
    const int mbase = by * 128, nbase = bx * 128;

    const float*  Af = x + (size_t)mbase * K;
    const __half* Bh = qwT + (size_t)nbase * K;

    int hr[2], hcu[2];
#pragma unroll
    for (int i = 0; i < 2; i++) {
        int idx = tid + i * 256;
        hr[i] = idx >> 2;
        hcu[i] = (idx & 3) << 2;
    }
    int lr[4], lc[4];
#pragma unroll
    for (int i = 0; i < 4; i++) {
        int idx = tid + i * 256;
        lr[i] = idx >> 3;
        lc[i] = (idx & 7) << 2;
    }
    const int S = K >> 5;

    float4 rA[4];
#pragma unroll
    for (int i = 0; i < 4; i++) rA[i] = *(const float4*)(Af + (size_t)lr[i] * K + lc[i]);
#pragma unroll
    for (int i = 0; i < 2; i++)
        cpa16(smem_u32(&Bs[0][hr[i]][hcu[i]]), Bh + (size_t)hr[i] * K + hcu[i] * 2);
    cp_commit();
#pragma unroll
    for (int i = 0; i < 4; i++)
        *(uint2*)&As[0][lr[i]][lc[i] >> 1] =
            make_uint2(pk2(rA[i].x, rA[i].y), pk2(rA[i].z, rA[i].w));

    float cs[4][4][4];
#pragma unroll
    for (int i = 0; i < 4; i++)
#pragma unroll
        for (int j = 0; j < 4; j++)
#pragma unroll
            for (int q = 0; q < 4; q++) cs[i][j][q] = 0.f;

    for (int s = 0; s < S; s++) {
        const int cb = s & 1, nb = (s + 1) & 1;
        if (s + 1 < S) {
            const int k0 = (s + 1) << 5;
#pragma unroll
            for (int i = 0; i < 4; i++)
                rA[i] = *(const float4*)(Af + (size_t)lr[i] * K + k0 + lc[i]);
#pragma unroll
            for (int i = 0; i < 2; i++)
                cpa16(smem_u32(&Bs[nb][hr[i]][hcu[i]]),
                      Bh + (size_t)hr[i] * K + k0 + hcu[i] * 2);
            cp_commit();
            cp_wait<1>();
        } else {
            cp_wait<0>();
        }
        __syncthreads();
#pragma unroll
        for (int ks = 0; ks < 2; ks++) {
            const int kk = ks * 8 + t;
            uint32_t af[4][4], bf[4][2];
#pragma unroll
            for (int mt = 0; mt < 4; mt++) {
                int row = wm * 64 + mt * 16;
                af[mt][0] = As[cb][row + g][kk];
                af[mt][1] = As[cb][row + g + 8][kk];
                af[mt][2] = As[cb][row + g][kk + 4];
                af[mt][3] = As[cb][row + g + 8][kk + 4];
            }
#pragma unroll
            for (int nt = 0; nt < 4; nt++) {
                int rb = wn * 32 + nt * 8 + g;
                bf[nt][0] = Bs[cb][rb][kk];
                bf[nt][1] = Bs[cb][rb][kk + 4];
            }
#pragma unroll
            for (int mt = 0; mt < 4; mt++)
#pragma unroll
                for (int nt = 0; nt < 4; nt++) mma16(cs[mt][nt], af[mt], bf[nt]);
        }
        __syncthreads();
        if (s + 1 < S) {
#pragma unroll
            for (int i = 0; i < 4; i++)
                *(uint2*)&As[nb][lr[i]][lc[i] >> 1] =
                    make_uint2(pk2(rA[i].x, rA[i].y), pk2(rA[i].z, rA[i].w));
        }
    }

    uint32_t* C = (uint32_t*)pq;
#pragma unroll
    for (int mt = 0; mt < 4; mt++) {
        int row0 = mbase + wm * 64 + mt * 16 + g;
#pragma unroll
        for (int nt = 0; nt < 4; nt++) {
            int col = nbase + wn * 32 + nt * 8 + 2 * t;
            C[((size_t)row0 * Nout + col) >> 1] = pk2(cs[mt][nt][0], cs[mt][nt][1]);
            C[((size_t)(row0 + 8) * Nout + col) >> 1] = pk2(cs[mt][nt][2], cs[mt][nt][3]);
        }
    }
}

// ===== conv body (4x4/stride4 im2col), split-K -> f32 partials =====
__device__ void conv_body(Tile* As, Tile* Bs, const float* __restrict__ x,
                          const __half* __restrict__ w2t, float* __restrict__ part,
                          int bx, int by, int kz) {
    const int tid = threadIdx.x, lane = tid & 31, warp = tid >> 5;
    const int g = lane >> 2, t = lane & 3;
    const int wm = warp >> 2, wn = warp & 3;
    const int mbase = by * 128, nbase = bx * 128;

    int hr[2], hcu[2];
#pragma unroll
    for (int i = 0; i < 2; i++) {
        int idx = tid + i * 256;
        hr[i] = idx >> 2;
        hcu[i] = (idx & 3) << 2;
    }
    int lr[4], lc[4], rowb[4];
#pragma unroll
    for (int i = 0; i < 4; i++) {
        int idx = tid + i * 256;
        lr[i] = idx >> 3;
        lc[i] = (idx & 7) << 2;
        int m = mbase + lr[i];
        int b = m >> 8, p = m & 255;
        rowb[i] = b * 4096 + (p >> 4) * 256 + (p & 15) * 4;
    }

    auto ldA = [&](int s, float4* r) {
        int kg = kz * 512 + s * 32;
        int pix = kg >> 8, cin0 = kg & 255;
        int pi = pix >> 2, pj = pix & 3;
#pragma unroll
        for (int i = 0; i < 4; i++)
            r[i] = *(const float4*)(x + (size_t)(rowb[i] + pi * 64 + pj) * 256 + cin0 + lc[i]);
    };
    auto cpB = [&](int s, int buf) {
        int kg = kz * 512 + s * 32;
#pragma unroll
        for (int i = 0; i < 2; i++)
            cpa16(smem_u32(&Bs[buf][hr[i]][hcu[i]]),
                  w2t + (size_t)(nbase + hr[i]) * 4096 + kg + hcu[i] * 2);
    };
    auto stA = [&](int buf, const float4* r) {
#pragma unroll
        for (int i = 0; i < 4; i++)
            *(uint2*)&As[buf][lr[i]][lc[i] >> 1] =
                make_uint2(pk2(r[i].x, r[i].y), pk2(r[i].z, r[i].w));
    };

    float4 rA[4];
    ldA(0, rA);
    cpB(0, 0);
    cp_commit();
    stA(0, rA);

    float cs[4][4][4];
#pragma unroll
    for (int i = 0; i < 4; i++)
#pragma unroll
        for (int j = 0; j < 4; j++)
#pragma unroll
            for (int q = 0; q < 4; q++) cs[i][j][q] = 0.f;

    for (int s = 0; s < 16; s++) {
        const int cb = s & 1, nb = (s + 1) & 1;
        if (s + 1 < 16) {
            ldA(s + 1, rA);
            cpB(s + 1, nb);
            cp_commit();
            cp_wait<1>();
        } else {
            cp_wait<0>();
        }
        __syncthreads();
#pragma unroll
        for (int ks = 0; ks < 2; ks++) {
            const int kk = ks * 8 + t;
            uint32_t af[4][4], bf[4][2];
#pragma unroll
            for (int mt = 0; mt < 4; mt++) {
                int row = wm * 64 + mt * 16;
                af[mt][0] = As[cb][row + g][kk];
                af[mt][1] = As[cb][row + g + 8][kk];
                af[mt][2] = As[cb][row + g][kk + 4];
                af[mt][3] = As[cb][row + g + 8][kk + 4];
            }
#pragma unroll
            for (int nt = 0; nt < 4; nt++) {
                int rb = wn * 32 + nt * 8 + g;
                bf[nt][0] = Bs[cb][rb][kk];
                bf[nt][1] = Bs[cb][rb][kk + 4];
            }
#pragma unroll
            for (int mt = 0; mt < 4; mt++)
#pragma unroll
                for (int nt = 0; nt < 4; nt++) mma16(cs[mt][nt], af[mt], bf[nt]);
        }
        __syncthreads();
        if (s + 1 < 16) stA(nb, rA);
    }

    float* outp = part + (size_t)kz * 2048 * 256;
#pragma unroll
    for (int mt = 0; mt < 4; mt++) {
        int row = mbase + wm * 64 + mt * 16 + g;
#pragma unroll
        for (int nt = 0; nt < 4; nt++) {
            int col = nbase + wn * 32 + nt * 8 + 2 * t;
            *(float2*)(outp + (size_t)row * 256 + col) = make_float2(cs[mt][nt][0], cs[mt][nt][1]);
            *(float2*)(outp + (size_t)(row + 8) * 256 + col) = make_float2(cs[mt][nt][2], cs[mt][nt][3]);
        }
    }
}

// ===== fused launch: conv (blocks 0..255) + q-gemm (blocks 256..767) =====
__global__ __launch_bounds__(256, 2)
void fused_qconv(const float* __restrict__ x, const __half* __restrict__ qwT,
                 const __half* __restrict__ w2t, __half* __restrict__ pq,
                 float* __restrict__ part) {
    __shared__ uint32_t As[2][128][20];
    __shared__ uint32_t Bs[2][128][20];
    int id = blockIdx.x;
    if (id < 256) {
        conv_body(As, Bs, x, w2t, part, id & 1, (id >> 1) & 15, id >> 5);
    } else {
        int u = id - 256;
        q_body(As, Bs, x, qwT, pq, u & 1, u >> 1);
    }
}

// ===== generic fp16 GEMM (kv + proj) =====
// MODE 0: f32 out + bias (proj).  MODE 2: kv split (K rows + V^T).
template <int MODE>
__global__ __launch_bounds__(256, 2)
void gemm_h(const __half* __restrict__ Ah0, const __half* __restrict__ Bt,
            const float* __restrict__ bias, void* __restrict__ Cp,
            __half* __restrict__ C2, int K, int Nout) {
    __shared__ uint32_t As[2][128][20];
    __shared__ uint32_t Bs[2][128][20];

    const int tid = threadIdx.x, lane = tid & 31, warp = tid >> 5;
    const int g = lane >> 2, t = lane & 3;
    const int wm = warp >> 2, wn = warp & 3;
    const int mbase = blockIdx.y * 128, nbase = blockIdx.x * 128;

    const __half* Ah = Ah0 + (size_t)mbase * K;
    const __half* Bh = Bt + (size_t)nbase * K;

    int hr[2], hcu[2];
#pragma unroll
    for (int i = 0; i < 2; i++) {
        int idx = tid + i * 256;
        hr[i] = idx >> 2;
        hcu[i] = (idx & 3) << 2;
    }
    const int S = K >> 5;

#pragma unroll
    for (int i = 0; i < 2; i++) {
        cpa16(smem_u32(&As[0][hr[i]][hcu[i]]), Ah + (size_t)hr[i] * K + hcu[i] * 2);
        cpa16(smem_u32(&Bs[0][hr[i]][hcu[i]]), Bh + (size_t)hr[i] * K + hcu[i] * 2);
    }
    cp_commit();

    float cs[4][4][4];
#pragma unroll
    for (int i = 0; i < 4; i++)
#pragma unroll
        for (int j = 0; j < 4; j++)
#pragma unroll
            for (int q = 0; q < 4; q++) cs[i][j][q] = 0.f;

    for (int s = 0; s < S; s++) {
        const int cb = s & 1, nb = (s + 1) & 1;
        if (s + 1 < S) {
            const int k0 = (s + 1) << 5;
#pragma unroll
            for (int i = 0; i < 2; i++) {
                cpa16(smem_u32(&As[nb][hr[i]][hcu[i]]), Ah + (size_t)hr[i] * K + k0 + hcu[i] * 2);
                cpa16(smem_u32(&Bs[nb][hr[i]][hcu[i]]), Bh + (size_t)hr[i] * K + k0 + hcu[i] * 2);
            }
            cp_commit();
            cp_wait<1>();
        } else {
            cp_wait<0>();
        }
        __syncthreads();
#pragma unroll
        for (int ks = 0; ks < 2; ks++) {
            const int kk = ks * 8 + t;
            uint32_t af[4][4], bf[4][2];
#pragma unroll
            for (int mt = 0; mt < 4; mt++) {
                int row = wm * 64 + mt * 16;
                af[mt][0] = As[cb][row + g][kk];
                af[mt][1] = As[cb][row + g + 8][kk];
                af[mt][2] = As[cb][row + g][kk + 4];
                af[mt][3] = As[cb][row + g + 8][kk + 4];
            }
#pragma unroll
            for (int nt = 0; nt < 4; nt++) {
                int rb = wn * 32 + nt * 8 + g;
                bf[nt][0] = Bs[cb][rb][kk];
                bf[nt][1] = Bs[cb][rb][kk + 4];
            }
#pragma unroll
            for (int mt = 0; mt < 4; mt++)
#pragma unroll
                for (int nt = 0; nt < 4; nt++) mma16(cs[mt][nt], af[mt], bf[nt]);
        }
        __syncthreads();
    }

#pragma unroll
    for (int mt = 0; mt < 4; mt++) {
        int row0 = mbase + wm * 64 + mt * 16 + g;
#pragma unroll
        for (int nt = 0; nt < 4; nt++) {
            int col = nbase + wn * 32 + nt * 8 + 2 * t;
            float v0 = cs[mt][nt][0], v1 = cs[mt][nt][1];
            float v2 = cs[mt][nt][2], v3 = cs[mt][nt][3];
            if (MODE == 0) {
                float b0 = __ldg(bias + col), b1 = __ldg(bias + col + 1);
                float* C = (float*)Cp;
                *(float2*)(C + (size_t)row0 * Nout + col) = make_float2(v0 + b0, v1 + b1);
                *(float2*)(C + (size_t)(row0 + 8) * Nout + col) = make_float2(v2 + b0, v3 + b1);
            } else {
                if (col < 256) {
                    uint32_t* C = (uint32_t*)Cp;
                    C[((size_t)row0 * 256 + col) >> 1] = pk2(v0, v1);
                    C[((size_t)(row0 + 8) * 256 + col) >> 1] = pk2(v2, v3);
                } else {
                    int dim = col - 256;
                    int h = dim >> 5, d = dim & 31;
                    int b0i = row0 >> 8, tok0 = row0 & 255;
                    size_t rbase = (size_t)((b0i * 8 + h) * 32 + d) * 256;
                    C2[rbase + tok0] = __float2half_rn(v0);
                    C2[rbase + 256 + tok0] = __float2half_rn(v1);
                    C2[rbase + tok0 + 8] = __float2half_rn(v2);
                    C2[rbase + 256 + tok0 + 8] = __float2half_rn(v3);
                }
            }
        }
    }
}

// ===== split-K reduce + bias + LayerNorm -> fp16 =====
__global__ void reduce_ln(const float* __restrict__ part, const float* __restrict__ bias,
                          const float* __restrict__ w, const float* __restrict__ bvec,
                          __half* __restrict__ xr) {
    __shared__ float red[18];
    const int r = blockIdx.x, c = threadIdx.x;
    float v = bias[c];
#pragma unroll
    for (int z = 0; z < SPLITK; z++)
        v += part[(size_t)z * 2048 * 256 + (size_t)r * 256 + c];
    float s1 = v, s2 = v * v;
#pragma unroll
    for (int off = 16; off; off >>= 1) {
        s1 += __shfl_xor_sync(~0u, s1, off);
        s2 += __shfl_xor_sync(~0u, s2, off);
    }
    int wid = c >> 5;
    if ((c & 31) == 0) { red[wid] = s1; red[8 + wid] = s2; }
    __syncthreads();
    if (c == 0) {
        float a = 0.f, q = 0.f;
#pragma unroll
        for (int i = 0; i < 8; i++) { a += red[i]; q += red[8 + i]; }
        red[16] = a; red[17] = q;
    }
    __syncthreads();
    float mu = red[16] * (1.0f / 256.0f);
    float var = red[17] * (1.0f / 256.0f) - mu * mu;
    float out = (v - mu) * rsqrtf(var + 1e-5f) * w[c] + bvec[c];
    xr[(size_t)r * 256 + c] = __float2half_rn(out);
}

// ===== flash fused attention, fp16 mma (m16n8k16), online softmax =====
__global__ __launch_bounds__(256, 2)
void attn_h(const __half* __restrict__ qh, const __half* __restrict__ kh,
            const __half* __restrict__ vth, __half* __restrict__ outp) {
    __shared__ uint32_t Ks[256][20];    // K tokens, 16 half2 + pad
    __shared__ uint32_t VsT[32][132];   // V^T [dim][tok/2], 128 half2 + pad
    __shared__ uint32_t Pw8[8][16][20]; // per-warp P panels

    const int tid = threadIdx.x, lane = tid & 31, warp = tid >> 5;
    const int g = lane >> 2, t = lane & 3;
    const int qt = blockIdx.x, h = blockIdx.y, b = blockIdx.z;
    const size_t qbase = (size_t)b * 4096 + (size_t)qt * 128;
    const int hoff = h * 32;
    uint32_t (*Pw)[20] = Pw8[warp];

    const __half* kbase = kh + (size_t)b * 256 * 256 + hoff;
    const __half* vbase = vth + (size_t)((b * 8 + h) * 32) * 256;
    for (int idx = tid; idx < 2048; idx += 256) {
        if (idx < 1024) {
            int tok = idx >> 2, cu = (idx & 3) << 2;
            cpa16(smem_u32(&Ks[tok][cu]), kbase + (size_t)tok * 256 + cu * 2);
        } else {
            int u = idx - 1024;
            int d = u >> 5, cu = (u & 31) << 2;
            cpa16(smem_u32(&VsT[d][cu]), vbase + (size_t)d * 256 + cu * 2);
        }
    }
    cp_commit();

    const int qr = (int)qbase + warp * 16 + g;
    const uint32_t* qp = (const uint32_t*)qh + (size_t)qr * 128 + (hoff >> 1);
    uint32_t aq[2][4];
#pragma unroll
    for (int ks = 0; ks < 2; ks++) {
        aq[ks][0] = qp[ks * 8 + t];
        aq[ks][1] = qp[8 * 128 + ks * 8 + t];
        aq[ks][2] = qp[ks * 8 + t + 4];
        aq[ks][3] = qp[8 * 128 + ks * 8 + t + 4];
    }
    cp_wait<0>();
    __syncthreads();

    float m_lo = -1e30f, m_hi = -1e30f, l_lo = 0.f, l_hi = 0.f;
    float o[4][4];
#pragma unroll
    for (int nt = 0; nt < 4; nt++)
#pragma unroll
        for (int q2 = 0; q2 < 4; q2++) o[nt][q2] = 0.f;

#pragma unroll
    for (int ch = 0; ch < 4; ch++) {
        float s[8][4];
#pragma unroll
        for (int j = 0; j < 8; j++)
#pragma unroll
            for (int q2 = 0; q2 < 4; q2++) s[j][q2] = 0.f;
#pragma unroll
        for (int ks = 0; ks < 2; ks++) {
            const int kk = ks * 8 + t;
#pragma unroll
            for (int j = 0; j < 8; j++) {
                const uint32_t* kr = Ks[ch * 64 + j * 8 + g];
                uint32_t bf[2] = {kr[kk], kr[kk + 4]};
                mma16(s[j], aq[ks], bf);
            }
        }
        float cm_lo = s[0][0], cm_hi = s[0][2];
#pragma unroll
        for (int j = 0; j < 8; j++) {
            cm_lo = fmaxf(cm_lo, fmaxf(s[j][0], s[j][1]));
            cm_hi = fmaxf(cm_hi, fmaxf(s[j][2], s[j][3]));
        }
        cm_lo = fmaxf(cm_lo, __shfl_xor_sync(~0u, cm_lo, 1));
        cm_lo = fmaxf(cm_lo, __shfl_xor_sync(~0u, cm_lo, 2));
        cm_hi = fmaxf(cm_hi, __shfl_xor_sync(~0u, cm_hi, 1));
        cm_hi = fmaxf(cm_hi, __shfl_xor_sync(~0u, cm_hi, 2));
        float nm_lo = fmaxf(m_lo, cm_lo), nm_hi = fmaxf(m_hi, cm_hi);
        float sc_lo = ex2((m_lo - nm_lo) * ATT_C2);
        float sc_hi = ex2((m_hi - nm_hi) * ATT_C2);
        m_lo = nm_lo; m_hi = nm_hi;
        float ps_lo = 0.f, ps_hi = 0.f;
#pragma unroll
        for (int j = 0; j < 8; j++) {
            s[j][0] = ex2((s[j][0] - m_lo) * ATT_C2);
            s[j][1] = ex2((s[j][1] - m_lo) * ATT_C2);
            s[j][2] = ex2((s[j][2] - m_hi) * ATT_C2);
            s[j][3] = ex2((s[j][3] - m_hi) * ATT_C2);
            ps_lo += s[j][0] + s[j][1];
            ps_hi += s[j][2] + s[j][3];
        }
        l_lo = l_lo * sc_lo + ps_lo;
        l_hi = l_hi * sc_hi + ps_hi;
#pragma unroll
        for (int nt = 0; nt < 4; nt++) {
            o[nt][0] *= sc_lo; o[nt][1] *= sc_lo;
            o[nt][2] *= sc_hi; o[nt][3] *= sc_hi;
        }
#pragma unroll
        for (int p2 = 0; p2 < 2; p2++) {
#pragma unroll
            for (int jj = 0; jj < 4; jj++) {
                const int j = p2 * 4 + jj;
                Pw[g][jj * 4 + t] = pk2(s[j][0], s[j][1]);
                Pw[g + 8][jj * 4 + t] = pk2(s[j][2], s[j][3]);
            }
            __syncwarp();
#pragma unroll
            for (int ks = 0; ks < 2; ks++) {
                uint32_t ap[4] = {Pw[g][ks * 8 + t], Pw[g + 8][ks * 8 + t],
                                  Pw[g][ks * 8 + t + 4], Pw[g + 8][ks * 8 + t + 4]};
                const int tu = (ch * 64 + p2 * 32 + ks * 16) >> 1;
#pragma unroll
                for (int nt = 0; nt < 4; nt++) {
                    const uint32_t* vr = VsT[nt * 8 + g];
                    uint32_t bf[2] = {vr[tu + t], vr[tu + 4 + t]};
                    mma16(o[nt], ap, bf);
                }
            }
            __syncwarp();
        }
    }

    l_lo += __shfl_xor_sync(~0u, l_lo, 1);
    l_lo += __shfl_xor_sync(~0u, l_lo, 2);
    l_hi += __shfl_xor_sync(~0u, l_hi, 1);
    l_hi += __shfl_xor_sync(~0u, l_hi, 2);
    const float rlo = 1.0f / l_lo, rhi = 1.0f / l_hi;

    uint32_t* op = (uint32_t*)outp + (size_t)qr * 128 + (hoff >> 1);
#pragma unroll
    for (int nt = 0; nt < 4; nt++) {
        op[nt * 4 + t] = pk2(o[nt][0] * rlo, o[nt][1] * rlo);
        op[8 * 128 + nt * 4 + t] = pk2(o[nt][2] * rhi, o[nt][3] * rhi);
    }
}

// ---------------- launch ----------------
extern "C" void kernel_launch(void* const* d_in, const int* in_sizes, int n_in,
                              void* d_out, int out_size) {
    const float* ptrs[9] = {nullptr};
    int pi = 0;
    for (int i = 0; i < n_in && pi < 9; i++) {
        if (in_sizes[i] == 1) continue;  // H, W scalars
        ptrs[pi++] = (const float*)d_in[i];
    }
    const float* x      = ptrs[0];
    const float* q_w    = ptrs[1];
    const float* kv_w   = ptrs[2];
    const float* sr_w   = ptrs[3];
    const float* sr_b   = ptrs[4];
    const float* ln_w   = ptrs[5];
    const float* ln_b   = ptrs[6];
    const float* proj_w = ptrs[7];
    const float* proj_b = ptrs[8];
    float* out = (float*)d_out;

    __half *pq, *pattn, *pxr, *pk, *pvt, *pqwT, *ppwT, *pkvwT, *pw2t;
    float* ppart;
    cudaGetSymbolAddress((void**)&pq, g_q);
    cudaGetSymbolAddress((void**)&pattn, g_attn);
    cudaGetSymbolAddress((void**)&pxr, g_xr);
    cudaGetSymbolAddress((void**)&pk, g_k);
    cudaGetSymbolAddress((void**)&pvt, g_vt);
    cudaGetSymbolAddress((void**)&pqwT, g_qwT);
    cudaGetSymbolAddress((void**)&ppwT, g_pwT);
    cudaGetSymbolAddress((void**)&pkvwT, g_kvwT);
    cudaGetSymbolAddress((void**)&pw2t, g_w2t);
    cudaGetSymbolAddress((void**)&ppart, g_part);

    // fused weight prep -> fp16
    prep_all<<<5120, 256>>>(q_w, proj_w, kv_w, sr_w, pqwT, ppwT, pkvwT, pw2t);
    // conv (split-K=8) + q-gemm in one launch
    fused_qconv<<<768, 256>>>(x, pqwT, pw2t, pq, ppart);
    // reduce + bias + LN -> fp16
    reduce_ln<<<2048, 256>>>(ppart, sr_b, ln_w, ln_b, pxr);
    // kv = xr @ kv_w -> K rows (fp16) + V^T (fp16)
    gemm_h<2><<<dim3(4, 16), 256>>>(pxr, pkvwT, nullptr, pk, pvt, 256, 512);
    // flash attention -> fp16
    attn_h<<<dim3(32, 8, 8), 256>>>(pq, pk, pvt, pattn);
    // out = attn @ proj_w + proj_b (f32)
    gemm_h<0><<<dim3(2, 256), 256>>>(pattn, ppwT, proj_b, out, nullptr, 256, 256);
}

// round 8
// speedup vs baseline: 5.9606x; 1.0266x over previous
#include <cuda_runtime.h>
#include <cuda_fp16.h>
#include <cstdint>

#define ATT_C2 0.25506238539520833f   // (1/sqrt(32)) * log2(e)
#define SPLITK 4

// ---------------- scratch (no allocation allowed) ----------------
__device__ __half g_q   [8 * 4096 * 256];   // q (fp16)
__device__ __half g_attn[8 * 4096 * 256];   // attention out (fp16)
__device__ __half g_xr  [2048 * 256];       // LN out (fp16)
__device__ __half g_k   [2048 * 256];       // K tokens (fp16) [b*256+tok][256]
__device__ __half g_vt  [64 * 32 * 256];    // V^T (fp16) [(b*8+h)*32+d][tok]
__device__ __half g_qwT [256 * 256];
__device__ __half g_pwT [256 * 256];
__device__ __half g_kvwT[512 * 256];
__device__ __half g_w2t [256 * 4096];       // conv weights [co][pix*256+cin]
__device__ float  g_part[SPLITK * 2048 * 256];

// ================= helpers =================
__device__ __forceinline__ uint32_t pk2(float a, float b) {
    __half2 h = __floats2half2_rn(a, b);
    return *reinterpret_cast<uint32_t*>(&h);
}
__device__ __forceinline__ float ex2(float x) {
    float y;
    asm("ex2.approx.f32 %0, %1;" : "=f"(y) : "f"(x));
    return y;
}
__device__ __forceinline__ uint32_t smem_u32(const void* p) {
    uint32_t a;
    asm("{ .reg .u64 t; cvta.to.shared.u64 t, %1; cvt.u32.u64 %0, t; }" : "=r"(a) : "l"(p));
    return a;
}
__device__ __forceinline__ void cpa16(uint32_t d, const void* s) {
    asm volatile("cp.async.ca.shared.global [%0], [%1], 16;" :: "r"(d), "l"(s) : "memory");
}
__device__ __forceinline__ void cp_commit() {
    asm volatile("cp.async.commit_group;" ::: "memory");
}
template <int N>
__device__ __forceinline__ void cp_wait() {
    asm volatile("cp.async.wait_group %0;" :: "n"(N) : "memory");
}
// D += A@B  (m16n8k16 fp16 in, fp32 acc)
__device__ __forceinline__ void mma16(float* d, const uint32_t* a, const uint32_t* b) {
    asm volatile(
        "mma.sync.aligned.m16n8k16.row.col.f32.f16.f16.f32 "
        "{%0,%1,%2,%3}, {%4,%5,%6,%7}, {%8,%9}, {%0,%1,%2,%3};"
        : "+f"(d[0]), "+f"(d[1]), "+f"(d[2]), "+f"(d[3])
        : "r"(a[0]), "r"(a[1]), "r"(a[2]), "r"(a[3]), "r"(b[0]), "r"(b[1]));
}

typedef uint32_t Tile[128][20];

// ===== fused weight prep: transposes + relayout, fp16 out =====
__global__ void prep_all(const float* __restrict__ qw, const float* __restrict__ pw,
                         const float* __restrict__ kvw, const float* __restrict__ srw,
                         __half* __restrict__ qwT, __half* __restrict__ pwT,
                         __half* __restrict__ kvwT, __half* __restrict__ w2t) {
    int t = blockIdx.x * 256 + threadIdx.x;
    if (t < 65536) {
        int n = t >> 8, k = t & 255;
        qwT[t] = __float2half_rn(qw[k * 256 + n]);
    } else if (t < 131072) {
        int u = t - 65536;
        int n = u >> 8, k = u & 255;
        pwT[u] = __float2half_rn(pw[k * 256 + n]);
    } else if (t < 262144) {
        int u = t - 131072;
        int n = u >> 8, k = u & 255;
        kvwT[u] = __float2half_rn(kvw[k * 512 + n]);
    } else {
        int u = t - 262144;  // < 1048576
        int co = u >> 12, rem = u & 4095;
        int pix = rem >> 8, cin = rem & 255;
        w2t[u] = __float2half_rn(srw[co * 4096 + cin * 16 + pix]);
    }
}

// ===== q-GEMM body: pq[M,256] = fp16(x[M,256] @ qwT^T), A f32 cvt =====
__device__ void q_body(Tile* As, Tile* Bs, const float* __restrict__ x,
                       const __half* __restrict__ qwT, __half* __restrict__ pq,
                       int bx, int by) {
    const int K = 256, Nout = 256;
    const int tid = threadIdx.x, lane = tid & 31, warp = tid >> 5;
    const int g = lane >> 2, t = lane & 3;
    const int wm = warp >> 2, wn = warp & 3;
    const int mbase = by * 128, nbase = bx * 128;

    const float*  Af = x + (size_t)mbase * K;
    const __half* Bh = qwT + (size_t)nbase * K;

    int hr[2], hcu[2];
#pragma unroll
    for (int i = 0; i < 2; i++) {
        int idx = tid + i * 256;
        hr[i] = idx >> 2;
        hcu[i] = (idx & 3) << 2;
    }
    int lr[4], lc[4];
#pragma unroll
    for (int i = 0; i < 4; i++) {
        int idx = tid + i * 256;
        lr[i] = idx >> 3;
        lc[i] = (idx & 7) << 2;
    }
    const int S = K >> 5;

    float4 rA[4];
#pragma unroll
    for (int i = 0; i < 4; i++) rA[i] = *(const float4*)(Af + (size_t)lr[i] * K + lc[i]);
#pragma unroll
    for (int i = 0; i < 2; i++)
        cpa16(smem_u32(&Bs[0][hr[i]][hcu[i]]), Bh + (size_t)hr[i] * K + hcu[i] * 2);
    cp_commit();
#pragma unroll
    for (int i = 0; i < 4; i++)
        *(uint2*)&As[0][lr[i]][lc[i] >> 1] =
            make_uint2(pk2(rA[i].x, rA[i].y), pk2(rA[i].z, rA[i].w));

    float cs[4][4][4];
#pragma unroll
    for (int i = 0; i < 4; i++)
#pragma unroll
        for (int j = 0; j < 4; j++)
#pragma unroll
            for (int q = 0; q < 4; q++) cs[i][j][q] = 0.f;

    for (int s = 0; s < S; s++) {
        const int cb = s & 1, nb = (s + 1) & 1;
        if (s + 1 < S) {
            const int k0 = (s + 1) << 5;
#pragma unroll
            for (int i = 0; i < 4; i++)
                rA[i] = *(const float4*)(Af + (size_t)lr[i] * K + k0 + lc[i]);
#pragma unroll
            for (int i = 0; i < 2; i++)
                cpa16(smem_u32(&Bs[nb][hr[i]][hcu[i]]),
                      Bh + (size_t)hr[i] * K + k0 + hcu[i] * 2);
            cp_commit();
            cp_wait<1>();
        } else {
            cp_wait<0>();
        }
        __syncthreads();
#pragma unroll
        for (int ks = 0; ks < 2; ks++) {
            const int kk = ks * 8 + t;
            uint32_t af[4][4], bf[4][2];
#pragma unroll
            for (int mt = 0; mt < 4; mt++) {
                int row = wm * 64 + mt * 16;
                af[mt][0] = As[cb][row + g][kk];
                af[mt][1] = As[cb][row + g + 8][kk];
                af[mt][2] = As[cb][row + g][kk + 4];
                af[mt][3] = As[cb][row + g + 8][kk + 4];
            }
#pragma unroll
            for (int nt = 0; nt < 4; nt++) {
                int rb = wn * 32 + nt * 8 + g;
                bf[nt][0] = Bs[cb][rb][kk];
                bf[nt][1] = Bs[cb][rb][kk + 4];
            }
#pragma unroll
            for (int mt = 0; mt < 4; mt++)
#pragma unroll
                for (int nt = 0; nt < 4; nt++) mma16(cs[mt][nt], af[mt], bf[nt]);
        }
        __syncthreads();
        if (s + 1 < S) {
#pragma unroll
            for (int i = 0; i < 4; i++)
                *(uint2*)&As[nb][lr[i]][lc[i] >> 1] =
                    make_uint2(pk2(rA[i].x, rA[i].y), pk2(rA[i].z, rA[i].w));
        }
    }

    uint32_t* C = (uint32_t*)pq;
#pragma unroll
    for (int mt = 0; mt < 4; mt++) {
        int row0 = mbase + wm * 64 + mt * 16 + g;
#pragma unroll
        for (int nt = 0; nt < 4; nt++) {
            int col = nbase + wn * 32 + nt * 8 + 2 * t;
            C[((size_t)row0 * Nout + col) >> 1] = pk2(cs[mt][nt][0], cs[mt][nt][1]);
            C[((size_t)(row0 + 8) * Nout + col) >> 1] = pk2(cs[mt][nt][2], cs[mt][nt][3]);
        }
    }
}

// ===== conv body (4x4/stride4 im2col), split-K=4 -> f32 partials =====
__device__ void conv_body(Tile* As, Tile* Bs, const float* __restrict__ x,
                          const __half* __restrict__ w2t, float* __restrict__ part,
                          int bx, int by, int kz) {
    const int tid = threadIdx.x, lane = tid & 31, warp = tid >> 5;
    const int g = lane >> 2, t = lane & 3;
    const int wm = warp >> 2, wn = warp & 3;
    const int mbase = by * 128, nbase = bx * 128;

    int hr[2], hcu[2];
#pragma unroll
    for (int i = 0; i < 2; i++) {
        int idx = tid + i * 256;
        hr[i] = idx >> 2;
        hcu[i] = (idx & 3) << 2;
    }
    int lr[4], lc[4], rowb[4];
#pragma unroll
    for (int i = 0; i < 4; i++) {
        int idx = tid + i * 256;
        lr[i] = idx >> 3;
        lc[i] = (idx & 7) << 2;
        int m = mbase + lr[i];
        int b = m >> 8, p = m & 255;
        rowb[i] = b * 4096 + (p >> 4) * 256 + (p & 15) * 4;
    }

    auto ldA = [&](int s, float4* r) {
        int kg = kz * 1024 + s * 32;
        int pix = kg >> 8, cin0 = kg & 255;
        int pi = pix >> 2, pj = pix & 3;
#pragma unroll
        for (int i = 0; i < 4; i++)
            r[i] = *(const float4*)(x + (size_t)(rowb[i] + pi * 64 + pj) * 256 + cin0 + lc[i]);
    };
    auto cpB = [&](int s, int buf) {
        int kg = kz * 1024 + s * 32;
#pragma unroll
        for (int i = 0; i < 2; i++)
            cpa16(smem_u32(&Bs[buf][hr[i]][hcu[i]]),
                  w2t + (size_t)(nbase + hr[i]) * 4096 + kg + hcu[i] * 2);
    };
    auto stA = [&](int buf, const float4* r) {
#pragma unroll
        for (int i = 0; i < 4; i++)
            *(uint2*)&As[buf][lr[i]][lc[i] >> 1] =
                make_uint2(pk2(r[i].x, r[i].y), pk2(r[i].z, r[i].w));
    };

    float4 rA[4];
    ldA(0, rA);
    cpB(0, 0);
    cp_commit();
    stA(0, rA);

    float cs[4][4][4];
#pragma unroll
    for (int i = 0; i < 4; i++)
#pragma unroll
        for (int j = 0; j < 4; j++)
#pragma unroll
            for (int q = 0; q < 4; q++) cs[i][j][q] = 0.f;

    for (int s = 0; s < 32; s++) {
        const int cb = s & 1, nb = (s + 1) & 1;
        if (s + 1 < 32) {
            ldA(s + 1, rA);
            cpB(s + 1, nb);
            cp_commit();
            cp_wait<1>();
        } else {
            cp_wait<0>();
        }
        __syncthreads();
#pragma unroll
        for (int ks = 0; ks < 2; ks++) {
            const int kk = ks * 8 + t;
            uint32_t af[4][4], bf[4][2];
#pragma unroll
            for (int mt = 0; mt < 4; mt++) {
                int row = wm * 64 + mt * 16;
                af[mt][0] = As[cb][row + g][kk];
                af[mt][1] = As[cb][row + g + 8][kk];
                af[mt][2] = As[cb][row + g][kk + 4];
                af[mt][3] = As[cb][row + g + 8][kk + 4];
            }
#pragma unroll
            for (int nt = 0; nt < 4; nt++) {
                int rb = wn * 32 + nt * 8 + g;
                bf[nt][0] = Bs[cb][rb][kk];
                bf[nt][1] = Bs[cb][rb][kk + 4];
            }
#pragma unroll
            for (int mt = 0; mt < 4; mt++)
#pragma unroll
                for (int nt = 0; nt < 4; nt++) mma16(cs[mt][nt], af[mt], bf[nt]);
        }
        __syncthreads();
        if (s + 1 < 32) stA(nb, rA);
    }

    float* outp = part + (size_t)kz * 2048 * 256;
#pragma unroll
    for (int mt = 0; mt < 4; mt++) {
        int row = mbase + wm * 64 + mt * 16 + g;
#pragma unroll
        for (int nt = 0; nt < 4; nt++) {
            int col = nbase + wn * 32 + nt * 8 + 2 * t;
            *(float2*)(outp + (size_t)row * 256 + col) = make_float2(cs[mt][nt][0], cs[mt][nt][1]);
            *(float2*)(outp + (size_t)(row + 8) * 256 + col) = make_float2(cs[mt][nt][2], cs[mt][nt][3]);
        }
    }
}

// ===== fused launch: conv (blocks 0..127, split-K=4) + q-gemm (blocks 128..639) =====
__global__ __launch_bounds__(256, 2)
void fused_qconv(const float* __restrict__ x, const __half* __restrict__ qwT,
                 const __half* __restrict__ w2t, __half* __restrict__ pq,
                 float* __restrict__ part) {
    __shared__ uint32_t As[2][128][20];
    __shared__ uint32_t Bs[2][128][20];
    int id = blockIdx.x;
    if (id < 128) {
        conv_body(As, Bs, x, w2t, part, id & 1, (id >> 1) & 15, id >> 5);
    } else {
        int u = id - 128;
        q_body(As, Bs, x, qwT, pq, u & 1, u >> 1);
    }
}

// ===== kv GEMM: 64x128 tiles, grid (4, 32) = 128 CTAs, K=256 =====
// out split: col<256 -> K rows (fp16), col>=256 -> V^T (fp16)
__global__ __launch_bounds__(256, 2)
void kv_h(const __half* __restrict__ Ah0, const __half* __restrict__ Bt,
          __half* __restrict__ Kout, __half* __restrict__ C2) {
    __shared__ uint32_t As[2][64][20];
    __shared__ uint32_t Bs[2][128][20];
    const int K = 256;

    const int tid = threadIdx.x, lane = tid & 31, warp = tid >> 5;
    const int g = lane >> 2, t = lane & 3;
    const int wm = warp >> 2, wn = warp & 3;   // wm in {0,1}: 32-row half
    const int mbase = blockIdx.y * 64, nbase = blockIdx.x * 128;

    const __half* Ah = Ah0 + (size_t)mbase * K;
    const __half* Bh = Bt + (size_t)nbase * K;

    const int ar = tid >> 2, acu = (tid & 3) << 2;   // A: 64 rows x 4 chunks
    int hr[2], hcu[2];
#pragma unroll
    for (int i = 0; i < 2; i++) {
        int idx = tid + i * 256;
        hr[i] = idx >> 2;
        hcu[i] = (idx & 3) << 2;
    }

    cpa16(smem_u32(&As[0][ar][acu]), Ah + (size_t)ar * K + acu * 2);
#pragma unroll
    for (int i = 0; i < 2; i++)
        cpa16(smem_u32(&Bs[0][hr[i]][hcu[i]]), Bh + (size_t)hr[i] * K + hcu[i] * 2);
    cp_commit();

    float cs[2][4][4];
#pragma unroll
    for (int i = 0; i < 2; i++)
#pragma unroll
        for (int j = 0; j < 4; j++)
#pragma unroll
            for (int q = 0; q < 4; q++) cs[i][j][q] = 0.f;

    for (int s = 0; s < 8; s++) {
        const int cb = s & 1, nb = (s + 1) & 1;
        if (s + 1 < 8) {
            const int k0 = (s + 1) << 5;
            cpa16(smem_u32(&As[nb][ar][acu]), Ah + (size_t)ar * K + k0 + acu * 2);
#pragma unroll
            for (int i = 0; i < 2; i++)
                cpa16(smem_u32(&Bs[nb][hr[i]][hcu[i]]), Bh + (size_t)hr[i] * K + k0 + hcu[i] * 2);
            cp_commit();
            cp_wait<1>();
        } else {
            cp_wait<0>();
        }
        __syncthreads();
#pragma unroll
        for (int ks = 0; ks < 2; ks++) {
            const int kk = ks * 8 + t;
            uint32_t af[2][4], bf[4][2];
#pragma unroll
            for (int mt = 0; mt < 2; mt++) {
                int row = wm * 32 + mt * 16;
                af[mt][0] = As[cb][row + g][kk];
                af[mt][1] = As[cb][row + g + 8][kk];
                af[mt][2] = As[cb][row + g][kk + 4];
                af[mt][3] = As[cb][row + g + 8][kk + 4];
            }
#pragma unroll
            for (int nt = 0; nt < 4; nt++) {
                int rb = wn * 32 + nt * 8 + g;
                bf[nt][0] = Bs[cb][rb][kk];
                bf[nt][1] = Bs[cb][rb][kk + 4];
            }
#pragma unroll
            for (int mt = 0; mt < 2; mt++)
#pragma unroll
                for (int nt = 0; nt < 4; nt++) mma16(cs[mt][nt], af[mt], bf[nt]);
        }
        __syncthreads();
    }

#pragma unroll
    for (int mt = 0; mt < 2; mt++) {
        int row0 = mbase + wm * 32 + mt * 16 + g;
#pragma unroll
        for (int nt = 0; nt < 4; nt++) {
            int col = nbase + wn * 32 + nt * 8 + 2 * t;
            float v0 = cs[mt][nt][0], v1 = cs[mt][nt][1];
            float v2 = cs[mt][nt][2], v3 = cs[mt][nt][3];
            if (col < 256) {
                uint32_t* C = (uint32_t*)Kout;
                C[((size_t)row0 * 256 + col) >> 1] = pk2(v0, v1);
                C[((size_t)(row0 + 8) * 256 + col) >> 1] = pk2(v2, v3);
            } else {
                int dim = col - 256;
                int h = dim >> 5, d = dim & 31;
                int b0i = row0 >> 8, tok0 = row0 & 255;
                size_t rbase = (size_t)((b0i * 8 + h) * 32 + d) * 256;
                C2[rbase + tok0] = __float2half_rn(v0);
                C2[rbase + 256 + tok0] = __float2half_rn(v1);
                C2[rbase + tok0 + 8] = __float2half_rn(v2);
                C2[rbase + 256 + tok0 + 8] = __float2half_rn(v3);
            }
        }
    }
}

// ===== proj GEMM: 128x128, f32 out + bias =====
__global__ __launch_bounds__(256, 2)
void proj_h(const __half* __restrict__ Ah0, const __half* __restrict__ Bt,
            const float* __restrict__ bias, float* __restrict__ C) {
    __shared__ uint32_t As[2][128][20];
    __shared__ uint32_t Bs[2][128][20];
    const int K = 256, Nout = 256;

    const int tid = threadIdx.x, lane = tid & 31, warp = tid >> 5;
    const int g = lane >> 2, t = lane & 3;
    const int wm = warp >> 2, wn = warp & 3;
    const int mbase = blockIdx.y * 128, nbase = blockIdx.x * 128;

    const __half* Ah = Ah0 + (size_t)mbase * K;
    const __half* Bh = Bt + (size_t)nbase * K;

    int hr[2], hcu[2];
#pragma unroll
    for (int i = 0; i < 2; i++) {
        int idx = tid + i * 256;
        hr[i] = idx >> 2;
        hcu[i] = (idx & 3) << 2;
    }
    const int S = K >> 5;

#pragma unroll
    for (int i = 0; i < 2; i++) {
        cpa16(smem_u32(&As[0][hr[i]][hcu[i]]), Ah + (size_t)hr[i] * K + hcu[i] * 2);
        cpa16(smem_u32(&Bs[0][hr[i]][hcu[i]]), Bh + (size_t)hr[i] * K + hcu[i] * 2);
    }
    cp_commit();

    float cs[4][4][4];
#pragma unroll
    for (int i = 0; i < 4; i++)
#pragma unroll
        for (int j = 0; j < 4; j++)
#pragma unroll
            for (int q = 0; q < 4; q++) cs[i][j][q] = 0.f;

    for (int s = 0; s < S; s++) {
        const int cb = s & 1, nb = (s + 1) & 1;
        if (s + 1 < S) {
            const int k0 = (s + 1) << 5;
#pragma unroll
            for (int i = 0; i < 2; i++) {
                cpa16(smem_u32(&As[nb][hr[i]][hcu[i]]), Ah + (size_t)hr[i] * K + k0 + hcu[i] * 2);
                cpa16(smem_u32(&Bs[nb][hr[i]][hcu[i]]), Bh + (size_t)hr[i] * K + k0 + hcu[i] * 2);
            }
            cp_commit();
            cp_wait<1>();
        } else {
            cp_wait<0>();
        }
        __syncthreads();
#pragma unroll
        for (int ks = 0; ks < 2; ks++) {
            const int kk = ks * 8 + t;
            uint32_t af[4][4], bf[4][2];
#pragma unroll
            for (int mt = 0; mt < 4; mt++) {
                int row = wm * 64 + mt * 16;
                af[mt][0] = As[cb][row + g][kk];
                af[mt][1] = As[cb][row + g + 8][kk];
                af[mt][2] = As[cb][row + g][kk + 4];
                af[mt][3] = As[cb][row + g + 8][kk + 4];
            }
#pragma unroll
            for (int nt = 0; nt < 4; nt++) {
                int rb = wn * 32 + nt * 8 + g;
                bf[nt][0] = Bs[cb][rb][kk];
                bf[nt][1] = Bs[cb][rb][kk + 4];
            }
#pragma unroll
            for (int mt = 0; mt < 4; mt++)
#pragma unroll
                for (int nt = 0; nt < 4; nt++) mma16(cs[mt][nt], af[mt], bf[nt]);
        }
        __syncthreads();
    }

#pragma unroll
    for (int mt = 0; mt < 4; mt++) {
        int row0 = mbase + wm * 64 + mt * 16 + g;
#pragma unroll
        for (int nt = 0; nt < 4; nt++) {
            int col = nbase + wn * 32 + nt * 8 + 2 * t;
            float b0 = __ldg(bias + col), b1 = __ldg(bias + col + 1);
            *(float2*)(C + (size_t)row0 * Nout + col) =
                make_float2(cs[mt][nt][0] + b0, cs[mt][nt][1] + b1);
            *(float2*)(C + (size_t)(row0 + 8) * Nout + col) =
                make_float2(cs[mt][nt][2] + b0, cs[mt][nt][3] + b1);
        }
    }
}

// ===== split-K reduce + bias + LayerNorm -> fp16 =====
__global__ void reduce_ln(const float* __restrict__ part, const float* __restrict__ bias,
                          const float* __restrict__ w, const float* __restrict__ bvec,
                          __half* __restrict__ xr) {
    __shared__ float red[18];
    const int r = blockIdx.x, c = threadIdx.x;
    float v = bias[c];
#pragma unroll
    for (int z = 0; z < SPLITK; z++)
        v += part[(size_t)z * 2048 * 256 + (size_t)r * 256 + c];
    float s1 = v, s2 = v * v;
#pragma unroll
    for (int off = 16; off; off >>= 1) {
        s1 += __shfl_xor_sync(~0u, s1, off);
        s2 += __shfl_xor_sync(~0u, s2, off);
    }
    int wid = c >> 5;
    if ((c & 31) == 0) { red[wid] = s1; red[8 + wid] = s2; }
    __syncthreads();
    if (c == 0) {
        float a = 0.f, q = 0.f;
#pragma unroll
        for (int i = 0; i < 8; i++) { a += red[i]; q += red[8 + i]; }
        red[16] = a; red[17] = q;
    }
    __syncthreads();
    float mu = red[16] * (1.0f / 256.0f);
    float var = red[17] * (1.0f / 256.0f) - mu * mu;
    float out = (v - mu) * rsqrtf(var + 1e-5f) * w[c] + bvec[c];
    xr[(size_t)r * 256 + c] = __float2half_rn(out);
}

// ===== flash fused attention, fp16 mma (m16n8k16), online softmax =====
__global__ __launch_bounds__(256, 2)
void attn_h(const __half* __restrict__ qh, const __half* __restrict__ kh,
            const __half* __restrict__ vth, __half* __restrict__ outp) {
    __shared__ uint32_t Ks[256][20];    // K tokens, 16 half2 + pad
    __shared__ uint32_t VsT[32][132];   // V^T [dim][tok/2], 128 half2 + pad
    __shared__ uint32_t Pw8[8][16][20]; // per-warp P panels

    const int tid = threadIdx.x, lane = tid & 31, warp = tid >> 5;
    const int g = lane >> 2, t = lane & 3;
    const int qt = blockIdx.x, h = blockIdx.y, b = blockIdx.z;
    const size_t qbase = (size_t)b * 4096 + (size_t)qt * 128;
    const int hoff = h * 32;
    uint32_t (*Pw)[20] = Pw8[warp];

    const __half* kbase = kh + (size_t)b * 256 * 256 + hoff;
    const __half* vbase = vth + (size_t)((b * 8 + h) * 32) * 256;
    for (int idx = tid; idx < 2048; idx += 256) {
        if (idx < 1024) {
            int tok = idx >> 2, cu = (idx & 3) << 2;
            cpa16(smem_u32(&Ks[tok][cu]), kbase + (size_t)tok * 256 + cu * 2);
        } else {
            int u = idx - 1024;
            int d = u >> 5, cu = (u & 31) << 2;
            cpa16(smem_u32(&VsT[d][cu]), vbase + (size_t)d * 256 + cu * 2);
        }
    }
    cp_commit();

    const int qr = (int)qbase + warp * 16 + g;
    const uint32_t* qp = (const uint32_t*)qh + (size_t)qr * 128 + (hoff >> 1);
    uint32_t aq[2][4];
#pragma unroll
    for (int ks = 0; ks < 2; ks++) {
        aq[ks][0] = qp[ks * 8 + t];
        aq[ks][1] = qp[8 * 128 + ks * 8 + t];
        aq[ks][2] = qp[ks * 8 + t + 4];
        aq[ks][3] = qp[8 * 128 + ks * 8 + t + 4];
    }
    cp_wait<0>();
    __syncthreads();

    float m_lo = -1e30f, m_hi = -1e30f, l_lo = 0.f, l_hi = 0.f;
    float o[4][4];
#pragma unroll
    for (int nt = 0; nt < 4; nt++)
#pragma unroll
        for (int q2 = 0; q2 < 4; q2++) o[nt][q2] = 0.f;

#pragma unroll
    for (int ch = 0; ch < 4; ch++) {
        float s[8][4];
#pragma unroll
        for (int j = 0; j < 8; j++)
#pragma unroll
            for (int q2 = 0; q2 < 4; q2++) s[j][q2] = 0.f;
#pragma unroll
        for (int ks = 0; ks < 2; ks++) {
            const int kk = ks * 8 + t;
#pragma unroll
            for (int j = 0; j < 8; j++) {
                const uint32_t* kr = Ks[ch * 64 + j * 8 + g];
                uint32_t bf[2] = {kr[kk], kr[kk + 4]};
                mma16(s[j], aq[ks], bf);
            }
        }
        float cm_lo = s[0][0], cm_hi = s[0][2];
#pragma unroll
        for (int j = 0; j < 8; j++) {
            cm_lo = fmaxf(cm_lo, fmaxf(s[j][0], s[j][1]));
            cm_hi = fmaxf(cm_hi, fmaxf(s[j][2], s[j][3]));
        }
        cm_lo = fmaxf(cm_lo, __shfl_xor_sync(~0u, cm_lo, 1));
        cm_lo = fmaxf(cm_lo, __shfl_xor_sync(~0u, cm_lo, 2));
        cm_hi = fmaxf(cm_hi, __shfl_xor_sync(~0u, cm_hi, 1));
        cm_hi = fmaxf(cm_hi, __shfl_xor_sync(~0u, cm_hi, 2));
        float nm_lo = fmaxf(m_lo, cm_lo), nm_hi = fmaxf(m_hi, cm_hi);
        float sc_lo = ex2((m_lo - nm_lo) * ATT_C2);
        float sc_hi = ex2((m_hi - nm_hi) * ATT_C2);
        m_lo = nm_lo; m_hi = nm_hi;
        float ps_lo = 0.f, ps_hi = 0.f;
#pragma unroll
        for (int j = 0; j < 8; j++) {
            s[j][0] = ex2((s[j][0] - m_lo) * ATT_C2);
            s[j][1] = ex2((s[j][1] - m_lo) * ATT_C2);
            s[j][2] = ex2((s[j][2] - m_hi) * ATT_C2);
            s[j][3] = ex2((s[j][3] - m_hi) * ATT_C2);
            ps_lo += s[j][0] + s[j][1];
            ps_hi += s[j][2] + s[j][3];
        }
        l_lo = l_lo * sc_lo + ps_lo;
        l_hi = l_hi * sc_hi + ps_hi;
#pragma unroll
        for (int nt = 0; nt < 4; nt++) {
            o[nt][0] *= sc_lo; o[nt][1] *= sc_lo;
            o[nt][2] *= sc_hi; o[nt][3] *= sc_hi;
        }
#pragma unroll
        for (int p2 = 0; p2 < 2; p2++) {
#pragma unroll
            for (int jj = 0; jj < 4; jj++) {
                const int j = p2 * 4 + jj;
                Pw[g][jj * 4 + t] = pk2(s[j][0], s[j][1]);
                Pw[g + 8][jj * 4 + t] = pk2(s[j][2], s[j][3]);
            }
            __syncwarp();
#pragma unroll
            for (int ks = 0; ks < 2; ks++) {
                uint32_t ap[4] = {Pw[g][ks * 8 + t], Pw[g + 8][ks * 8 + t],
                                  Pw[g][ks * 8 + t + 4], Pw[g + 8][ks * 8 + t + 4]};
                const int tu = (ch * 64 + p2 * 32 + ks * 16) >> 1;
#pragma unroll
                for (int nt = 0; nt < 4; nt++) {
                    const uint32_t* vr = VsT[nt * 8 + g];
                    uint32_t bf[2] = {vr[tu + t], vr[tu + 4 + t]};
                    mma16(o[nt], ap, bf);
                }
            }
            __syncwarp();
        }
    }

    l_lo += __shfl_xor_sync(~0u, l_lo, 1);
    l_lo += __shfl_xor_sync(~0u, l_lo, 2);
    l_hi += __shfl_xor_sync(~0u, l_hi, 1);
    l_hi += __shfl_xor_sync(~0u, l_hi, 2);
    const float rlo = 1.0f / l_lo, rhi = 1.0f / l_hi;

    uint32_t* op = (uint32_t*)outp + (size_t)qr * 128 + (hoff >> 1);
#pragma unroll
    for (int nt = 0; nt < 4; nt++) {
        op[nt * 4 + t] = pk2(o[nt][0] * rlo, o[nt][1] * rlo);
        op[8 * 128 + nt * 4 + t] = pk2(o[nt][2] * rhi, o[nt][3] * rhi);
    }
}

// ---------------- launch ----------------
extern "C" void kernel_launch(void* const* d_in, const int* in_sizes, int n_in,
                              void* d_out, int out_size) {
    const float* ptrs[9] = {nullptr};
    int pi = 0;
    for (int i = 0; i < n_in && pi < 9; i++) {
        if (in_sizes[i] == 1) continue;  // H, W scalars
        ptrs[pi++] = (const float*)d_in[i];
    }
    const float* x      = ptrs[0];
    const float* q_w    = ptrs[1];
    const float* kv_w   = ptrs[2];
    const float* sr_w   = ptrs[3];
    const float* sr_b   = ptrs[4];
    const float* ln_w   = ptrs[5];
    const float* ln_b   = ptrs[6];
    const float* proj_w = ptrs[7];
    const float* proj_b = ptrs[8];
    float* out = (float*)d_out;

    __half *pq, *pattn, *pxr, *pk, *pvt, *pqwT, *ppwT, *pkvwT, *pw2t;
    float* ppart;
    cudaGetSymbolAddress((void**)&pq, g_q);
    cudaGetSymbolAddress((void**)&pattn, g_attn);
    cudaGetSymbolAddress((void**)&pxr, g_xr);
    cudaGetSymbolAddress((void**)&pk, g_k);
    cudaGetSymbolAddress((void**)&pvt, g_vt);
    cudaGetSymbolAddress((void**)&pqwT, g_qwT);
    cudaGetSymbolAddress((void**)&ppwT, g_pwT);
    cudaGetSymbolAddress((void**)&pkvwT, g_kvwT);
    cudaGetSymbolAddress((void**)&pw2t, g_w2t);
    cudaGetSymbolAddress((void**)&ppart, g_part);

    // fused weight prep -> fp16
    prep_all<<<5120, 256>>>(q_w, proj_w, kv_w, sr_w, pqwT, ppwT, pkvwT, pw2t);
    // conv (split-K=4) + q-gemm in one launch
    fused_qconv<<<640, 256>>>(x, pqwT, pw2t, pq, ppart);
    // reduce + bias + LN -> fp16
    reduce_ln<<<2048, 256>>>(ppart, sr_b, ln_w, ln_b, pxr);
    // kv = xr @ kv_w -> K rows (fp16) + V^T (fp16); 64x128 tiles, 128 CTAs
    kv_h<<<dim3(4, 32), 256>>>(pxr, pkvwT, pk, pvt);
    // flash attention -> fp16
    attn_h<<<dim3(32, 8, 8), 256>>>(pq, pk, pvt, pattn);
    // out = attn @ proj_w + proj_b (f32)
    proj_h<<<dim3(2, 256), 256>>>(pattn, ppwT, proj_b, out);
}